// round 6
// baseline (speedup 1.0000x reference)
#include <cuda_runtime.h>
#include <math.h>

// Problem constants
#define BB      2
#define SS      2048
#define HIDC    4096
#define NHC     32
#define NKVC    8
#define HDC     128
#define MROWS   (BB*SS)          // 4096

// ---------------------------------------------------------------------------
// Scratch (device globals: the sanctioned alloc-free scratch path)
// ---------------------------------------------------------------------------
__device__ float g_q  [(size_t)MROWS * HIDC];        // [B,S,NH,HD]   64 MiB
__device__ float g_k  [(size_t)MROWS * NKVC * HDC];  // [B,S,NKV,HD]  16 MiB
__device__ float g_v  [(size_t)MROWS * NKVC * HDC];  // [B,S,NKV,HD]  16 MiB
__device__ float g_att[(size_t)MROWS * HIDC];        // [B,S,NH,HD]   64 MiB

// ---------------------------------------------------------------------------
// FP32 SGEMM: C[M,N] = A[M,K] @ W[K,N] (+ bias[N])
// 128x128 block tile, BK=16, 256 threads, 8x8 micro-tile, reg-prefetch pipeline
// ---------------------------------------------------------------------------
__global__ void __launch_bounds__(256, 2)
sgemm_bias(const float* __restrict__ A, const float* __restrict__ W,
           const float* __restrict__ bias, float* __restrict__ C,
           int N, int K)
{
    __shared__ float As[16][128];   // transposed: As[k][m]
    __shared__ float Bs[16][128];

    const int tid  = threadIdx.x;
    const int row0 = blockIdx.y * 128;
    const int col0 = blockIdx.x * 128;
    const int tx   = tid & 15;
    const int ty   = tid >> 4;

    // per-thread global load bases
    const float* Aptr = A + (size_t)(row0 + (tid >> 2)) * K + ((tid & 3) << 2);
    const float* Bptr = W + (size_t)(tid >> 5) * N + col0 + ((tid & 31) << 2);

    float4 a0 = *(const float4*)(Aptr);
    float4 a1 = *(const float4*)(Aptr + (size_t)64 * K);
    float4 b0 = *(const float4*)(Bptr);
    float4 b1 = *(const float4*)(Bptr + (size_t)8 * N);

    float acc[8][8];
    #pragma unroll
    for (int i = 0; i < 8; i++)
        #pragma unroll
        for (int j = 0; j < 8; j++) acc[i][j] = 0.f;

    const int ntk = K >> 4;
    const int ra  = tid >> 2;
    const int ka  = (tid & 3) << 2;
    const int kb  = tid >> 5;
    const int nb  = (tid & 31) << 2;

    for (int kt = 0; kt < ntk; kt++) {
        // regs -> smem (A transposed)
        As[ka + 0][ra]      = a0.x; As[ka + 1][ra]      = a0.y;
        As[ka + 2][ra]      = a0.z; As[ka + 3][ra]      = a0.w;
        As[ka + 0][ra + 64] = a1.x; As[ka + 1][ra + 64] = a1.y;
        As[ka + 2][ra + 64] = a1.z; As[ka + 3][ra + 64] = a1.w;
        *(float4*)&Bs[kb][nb]     = b0;
        *(float4*)&Bs[kb + 8][nb] = b1;
        __syncthreads();

        // prefetch next tile (hidden under 1024 FMAs)
        if (kt + 1 < ntk) {
            const int ko = (kt + 1) << 4;
            a0 = *(const float4*)(Aptr + ko);
            a1 = *(const float4*)(Aptr + (size_t)64 * K + ko);
            b0 = *(const float4*)(Bptr + (size_t)ko * N);
            b1 = *(const float4*)(Bptr + (size_t)ko * N + (size_t)8 * N);
        }

        #pragma unroll
        for (int kk = 0; kk < 16; kk++) {
            float ar[8], br[8];
            *(float4*)&ar[0] = *(const float4*)&As[kk][ty * 4];
            *(float4*)&ar[4] = *(const float4*)&As[kk][64 + ty * 4];
            *(float4*)&br[0] = *(const float4*)&Bs[kk][tx * 4];
            *(float4*)&br[4] = *(const float4*)&Bs[kk][64 + tx * 4];
            #pragma unroll
            for (int i = 0; i < 8; i++)
                #pragma unroll
                for (int j = 0; j < 8; j++)
                    acc[i][j] = fmaf(ar[i], br[j], acc[i][j]);
        }
        __syncthreads();
    }

    // epilogue: bias + store
    #pragma unroll
    for (int i = 0; i < 8; i++) {
        const int r = row0 + ((i < 4) ? (ty * 4 + i) : (64 + ty * 4 + i - 4));
        float* crow = C + (size_t)r * N;
        #pragma unroll
        for (int jh = 0; jh < 2; jh++) {
            const int c = col0 + jh * 64 + tx * 4;
            float4 v;
            v.x = acc[i][jh * 4 + 0]; v.y = acc[i][jh * 4 + 1];
            v.z = acc[i][jh * 4 + 2]; v.w = acc[i][jh * 4 + 3];
            if (bias) {
                float4 bv = *(const float4*)(bias + c);
                v.x += bv.x; v.y += bv.y; v.z += bv.z; v.w += bv.w;
            }
            *(float4*)(crow + c) = v;
        }
    }
}

// ---------------------------------------------------------------------------
// RoPE (in place): x[B,S,nheads,HD]; cos/sin [B,S,HD]
// out[d]    = x[d]*c[d]    - x[d+64]*s[d]     (d < 64)
// out[d+64] = x[d+64]*c[d+64] + x[d]*s[d+64]
// ---------------------------------------------------------------------------
__global__ void rope_kernel(float* __restrict__ x, const float* __restrict__ cs,
                            const float* __restrict__ sn, int nheads, int total)
{
    int p = blockIdx.x * blockDim.x + threadIdx.x;
    if (p >= total) return;
    const int d    = p & 63;
    const int h    = (p >> 6) % nheads;
    const int sidx = p / (64 * nheads);                 // b*S + s
    const size_t base = ((size_t)sidx * nheads + h) * HDC;
    const size_t cb   = (size_t)sidx * HDC;
    const float x1 = x[base + d];
    const float x2 = x[base + d + 64];
    const float c1 = cs[cb + d],      s1 = sn[cb + d];
    const float c2 = cs[cb + d + 64], s2 = sn[cb + d + 64];
    x[base + d]      = x1 * c1 - x2 * s1;
    x[base + d + 64] = x2 * c2 + x1 * s2;
}

// ---------------------------------------------------------------------------
// Flash attention (fp32, no mask): per (b, h, q-tile of 64 rows).
// 256 threads; thread t -> q-row r = t/4, lane quarter c4 = t&3.
// Scores: each thread owns 16 k-cols (j = 4*jj + c4).
// PV:     each thread owns 32 out-cols (float4 groups c4 + 4*cc).
// K and V share one smem buffer (load K -> scores -> load V -> PV).
// ---------------------------------------------------------------------------
#define LDT 132   // padded tile stride (floats), 16B-aligned, conflict-free
#define LDP 68    // padded P stride
#define ATTN_SMEM ((2 * 64 * LDT + 64 * LDP) * 4)   // 84992 bytes

__global__ void __launch_bounds__(256, 2)
attn_kernel(const float* __restrict__ Q, const float* __restrict__ Kk,
            const float* __restrict__ V, float* __restrict__ O)
{
    extern __shared__ float sm[];
    float* Qs  = sm;                  // [64][LDT]
    float* KVs = sm + 64 * LDT;       // [64][LDT]  (K, then reused for V)
    float* P   = sm + 2 * 64 * LDT;   // [64][LDP]

    const int tid = threadIdx.x;
    const int qt  = blockIdx.x;
    const int h   = blockIdx.y;
    const int b   = blockIdx.z;
    const int kv  = h >> 2;                 // GQA: h / GROUPS
    const int r   = tid >> 2;
    const int c4  = tid & 3;
    const float scale = 0.08838834764831845f;   // 1/sqrt(128)

    // ---- load Q tile (64 x 128) ----
    const float* qb = Q + ((size_t)(b * SS + qt * 64) * NHC + h) * HDC;
    #pragma unroll
    for (int i = 0; i < 8; i++) {
        const int s = tid + (i << 8);
        const int row = s >> 5, d4 = s & 31;
        *(float4*)(Qs + row * LDT + (d4 << 2)) =
            *(const float4*)(qb + (size_t)row * (NHC * HDC) + (d4 << 2));
    }

    float  m = -INFINITY, l = 0.f;
    float4 oacc[8];
    #pragma unroll
    for (int i = 0; i < 8; i++) oacc[i] = make_float4(0.f, 0.f, 0.f, 0.f);

    const size_t kvstride = (size_t)NKVC * HDC;
    const float* kbase0 = Kk + ((size_t)(b * SS) * NKVC + kv) * HDC;
    const float* vbase0 = V  + ((size_t)(b * SS) * NKVC + kv) * HDC;

    for (int kt = 0; kt < SS / 64; kt++) {
        // ---- load K tile ----
        __syncthreads();   // previous PV done with KVs (and Q visible on kt=0)
        {
            const float* kb = kbase0 + (size_t)kt * 64 * kvstride;
            #pragma unroll
            for (int i = 0; i < 8; i++) {
                const int s = tid + (i << 8);
                const int row = s >> 5, d4 = s & 31;
                *(float4*)(KVs + row * LDT + (d4 << 2)) =
                    *(const float4*)(kb + (size_t)row * kvstride + (d4 << 2));
            }
        }
        __syncthreads();

        // ---- scores: sc[jj] = Q[r,:] . K[4jj+c4,:] ----
        float sc[16];
        #pragma unroll
        for (int jj = 0; jj < 16; jj++) sc[jj] = 0.f;
        const float4* qrow = (const float4*)(Qs + r * LDT);
        #pragma unroll 4
        for (int d4 = 0; d4 < 32; d4++) {
            const float4 q4 = qrow[d4];
            #pragma unroll
            for (int jj = 0; jj < 16; jj++) {
                const float4 k4 = *((const float4*)(KVs + (jj * 4 + c4) * LDT) + d4);
                sc[jj] = fmaf(q4.x, k4.x,
                         fmaf(q4.y, k4.y,
                         fmaf(q4.z, k4.z,
                         fmaf(q4.w, k4.w, sc[jj]))));
            }
        }

        // ---- online softmax ----
        float tmax = -INFINITY;
        #pragma unroll
        for (int jj = 0; jj < 16; jj++) { sc[jj] *= scale; tmax = fmaxf(tmax, sc[jj]); }
        tmax = fmaxf(tmax, __shfl_xor_sync(0xffffffffu, tmax, 1));
        tmax = fmaxf(tmax, __shfl_xor_sync(0xffffffffu, tmax, 2));
        const float mnew = fmaxf(m, tmax);
        const float corr = __expf(m - mnew);          // exp(-inf)=0 on first tile
        float lsum = 0.f;
        #pragma unroll
        for (int jj = 0; jj < 16; jj++) {
            const float e = __expf(sc[jj] - mnew);
            P[r * LDP + jj * 4 + c4] = e;
            lsum += e;
        }
        lsum += __shfl_xor_sync(0xffffffffu, lsum, 1);
        lsum += __shfl_xor_sync(0xffffffffu, lsum, 2);
        l = l * corr + lsum;
        m = mnew;
        #pragma unroll
        for (int i = 0; i < 8; i++) {
            oacc[i].x *= corr; oacc[i].y *= corr;
            oacc[i].z *= corr; oacc[i].w *= corr;
        }

        // ---- load V tile into the same buffer ----
        __syncthreads();   // everyone done reading K
        {
            const float* vb = vbase0 + (size_t)kt * 64 * kvstride;
            #pragma unroll
            for (int i = 0; i < 8; i++) {
                const int s = tid + (i << 8);
                const int row = s >> 5, d4 = s & 31;
                *(float4*)(KVs + row * LDT + (d4 << 2)) =
                    *(const float4*)(vb + (size_t)row * kvstride + (d4 << 2));
            }
        }
        __syncthreads();

        // ---- PV: oacc[r, owned cols] += P[r,j] * V[j, cols] ----
        #pragma unroll 2
        for (int j = 0; j < 64; j++) {
            const float p = P[r * LDP + j];
            const float4* vr = (const float4*)(KVs + j * LDT);
            #pragma unroll
            for (int cc = 0; cc < 8; cc++) {
                const float4 v4 = vr[c4 + cc * 4];
                oacc[cc].x = fmaf(p, v4.x, oacc[cc].x);
                oacc[cc].y = fmaf(p, v4.y, oacc[cc].y);
                oacc[cc].z = fmaf(p, v4.z, oacc[cc].z);
                oacc[cc].w = fmaf(p, v4.w, oacc[cc].w);
            }
        }
    }

    // ---- normalize and store ----
    const float inv = 1.f / l;
    float* ob = O + ((size_t)(b * SS + qt * 64 + r) * NHC + h) * HDC;
    #pragma unroll
    for (int cc = 0; cc < 8; cc++) {
        float4 v = oacc[cc];
        v.x *= inv; v.y *= inv; v.z *= inv; v.w *= inv;
        *(float4*)(ob + ((c4 + cc * 4) << 2)) = v;
    }
}

// ---------------------------------------------------------------------------
// Launch
// ---------------------------------------------------------------------------
extern "C" void kernel_launch(void* const* d_in, const int* in_sizes, int n_in,
                              void* d_out, int out_size)
{
    (void)in_sizes; (void)n_in; (void)out_size;
    const float* hidden = (const float*)d_in[0];
    const float* cosp   = (const float*)d_in[1];
    const float* sinp   = (const float*)d_in[2];
    const float* Wq     = (const float*)d_in[3];
    const float* bq     = (const float*)d_in[4];
    const float* Wk     = (const float*)d_in[5];
    const float* bk     = (const float*)d_in[6];
    const float* Wv     = (const float*)d_in[7];
    const float* bv     = (const float*)d_in[8];
    const float* Wo     = (const float*)d_in[9];
    float* out = (float*)d_out;

    float *q, *k, *v, *att;
    cudaGetSymbolAddress((void**)&q,   g_q);
    cudaGetSymbolAddress((void**)&k,   g_k);
    cudaGetSymbolAddress((void**)&v,   g_v);
    cudaGetSymbolAddress((void**)&att, g_att);

    cudaFuncSetAttribute(attn_kernel,
                         cudaFuncAttributeMaxDynamicSharedMemorySize, ATTN_SMEM);

    const dim3 blk(256);
    // QKV projections (+bias)
    sgemm_bias<<<dim3(HIDC / 128, MROWS / 128), blk>>>(hidden, Wq, bq, q, HIDC, HIDC);
    sgemm_bias<<<dim3((NKVC * HDC) / 128, MROWS / 128), blk>>>(hidden, Wk, bk, k, NKVC * HDC, HIDC);
    sgemm_bias<<<dim3((NKVC * HDC) / 128, MROWS / 128), blk>>>(hidden, Wv, bv, v, NKVC * HDC, HIDC);

    // RoPE on q and k
    const int tq = MROWS * NHC * 64;
    rope_kernel<<<(tq + 255) / 256, 256>>>(q, cosp, sinp, NHC, tq);
    const int tk = MROWS * NKVC * 64;
    rope_kernel<<<(tk + 255) / 256, 256>>>(k, cosp, sinp, NKVC, tk);

    // Attention
    attn_kernel<<<dim3(SS / 64, NHC, BB), 256, ATTN_SMEM>>>(q, k, v, att);

    // Output projection (no bias)
    sgemm_bias<<<dim3(HIDC / 128, MROWS / 128), blk>>>(att, Wo, nullptr, out, HIDC, HIDC);
}

// round 8
// speedup vs baseline: 1.2773x; 1.2773x over previous
#include <cuda_runtime.h>
#include <cuda_bf16.h>
#include <stdint.h>
#include <math.h>

// Problem constants
#define BB      2
#define SS      2048
#define HIDC    4096
#define NHC     32
#define NKVC    8
#define HDC     128
#define MROWS   (BB*SS)          // 4096
#define KVW     (2*NKVC*HDC)     // 2048 combined K|V row width
#define GK      4096             // reduction dim for every projection

typedef __nv_bfloat16 bf16;

// ---------------------------------------------------------------------------
// Scratch (device globals: the sanctioned alloc-free scratch path)
// ---------------------------------------------------------------------------
__device__ bf16  g_ah [(size_t)MROWS * HIDC];   // hidden hi   32 MiB
__device__ bf16  g_al [(size_t)MROWS * HIDC];   // hidden lo   32 MiB
__device__ bf16  g_wqh[(size_t)HIDC * GK];      // Wq^T hi [N][K]
__device__ bf16  g_wql[(size_t)HIDC * GK];
__device__ bf16  g_wkh[(size_t)(NKVC*HDC) * GK];
__device__ bf16  g_wkl[(size_t)(NKVC*HDC) * GK];
__device__ bf16  g_wvh[(size_t)(NKVC*HDC) * GK];
__device__ bf16  g_wvl[(size_t)(NKVC*HDC) * GK];
__device__ bf16  g_woh[(size_t)HIDC * GK];
__device__ bf16  g_wol[(size_t)HIDC * GK];
__device__ bf16  g_oth[(size_t)MROWS * HIDC];   // att hi
__device__ bf16  g_otl[(size_t)MROWS * HIDC];   // att lo
__device__ float g_q  [(size_t)MROWS * HIDC];   // 64 MiB
__device__ float g_kv [(size_t)MROWS * KVW];    // 32 MiB  [row][K(1024)|V(1024)]
__device__ float g_att[(size_t)MROWS * HIDC];   // 64 MiB

// ---------------------------------------------------------------------------
// small helpers
// ---------------------------------------------------------------------------
__device__ __forceinline__ uint32_t smem_u32(const void* p) {
    uint32_t a;
    asm("{ .reg .u64 t; cvta.to.shared.u64 t, %1; cvt.u32.u64 %0, t; }" : "=r"(a) : "l"(p));
    return a;
}
__device__ __forceinline__ uint64_t gmem_u64(const void* p) {
    uint64_t a;
    asm("cvta.to.global.u64 %0, %1;" : "=l"(a) : "l"(p));
    return a;
}
#define CP16(smaddr, gaddr) \
    asm volatile("cp.async.cg.shared.global [%0], [%1], 16;" :: "r"(smaddr), "l"(gaddr) : "memory")

#define MMA16816(d, a, b) \
    asm volatile("mma.sync.aligned.m16n8k16.row.col.f32.bf16.bf16.f32 " \
        "{%0,%1,%2,%3}, {%4,%5,%6,%7}, {%8,%9}, {%0,%1,%2,%3};" \
        : "+f"((d)[0]), "+f"((d)[1]), "+f"((d)[2]), "+f"((d)[3]) \
        : "r"((a)[0]), "r"((a)[1]), "r"((a)[2]), "r"((a)[3]), \
          "r"((b)[0]), "r"((b)[1]))

// ---------------------------------------------------------------------------
// Pre-pass: split fp32 -> (hi, lo) bf16, same layout.  n4 = elems/4
// ---------------------------------------------------------------------------
__global__ void split_kernel(const float* __restrict__ x, bf16* __restrict__ h,
                             bf16* __restrict__ l, int n4)
{
    int i = blockIdx.x * blockDim.x + threadIdx.x;
    if (i >= n4) return;
    const float4 v = ((const float4*)x)[i];
    bf16 h0 = __float2bfloat16(v.x), h1 = __float2bfloat16(v.y);
    bf16 h2 = __float2bfloat16(v.z), h3 = __float2bfloat16(v.w);
    bf16 l0 = __float2bfloat16(v.x - __bfloat162float(h0));
    bf16 l1 = __float2bfloat16(v.y - __bfloat162float(h1));
    bf16 l2 = __float2bfloat16(v.z - __bfloat162float(h2));
    bf16 l3 = __float2bfloat16(v.w - __bfloat162float(h3));
    ((__nv_bfloat162*)h)[2*i]     = __halves2bfloat162(h0, h1);
    ((__nv_bfloat162*)h)[2*i + 1] = __halves2bfloat162(h2, h3);
    ((__nv_bfloat162*)l)[2*i]     = __halves2bfloat162(l0, l1);
    ((__nv_bfloat162*)l)[2*i + 1] = __halves2bfloat162(l2, l3);
}

// ---------------------------------------------------------------------------
// Pre-pass: W[k][n] fp32 -> Wt_hi/Wt_lo [n][k] bf16  (K = GK rows)
// ---------------------------------------------------------------------------
__global__ void wsplitT_kernel(const float* __restrict__ W, bf16* __restrict__ th,
                               bf16* __restrict__ tl, int Ncols)
{
    __shared__ float t[32][33];
    const int bx = blockIdx.x * 32, by = blockIdx.y * 32;
    const int tx = threadIdx.x, ty = threadIdx.y;
    #pragma unroll
    for (int i = 0; i < 4; i++)
        t[ty + i * 8][tx] = W[(size_t)(by + ty + i * 8) * Ncols + bx + tx];
    __syncthreads();
    #pragma unroll
    for (int i = 0; i < 4; i++) {
        const float v = t[tx][ty + i * 8];
        const size_t o = (size_t)(bx + ty + i * 8) * GK + by + tx;
        const bf16 h = __float2bfloat16(v);
        th[o] = h;
        tl[o] = __float2bfloat16(v - __bfloat162float(h));
    }
}

// ---------------------------------------------------------------------------
// 3x bf16-split GEMM via mma.sync (fallback HMMA path; tcgen05 PTX is
// rejected by ptxas at compute_103).
// C[M][N] = A[M][GK] @ Bt[N][GK]^T (+bias), fp32 accumulate.
// CTA tile 128x128, BK=32, 8 warps (2x4) of 64x32, 3-stage cp.async pipeline.
// smem per stage: Ah|Al|Bh|Bl, each 128 rows x 40 bf16 (padded, conflict-free)
// ---------------------------------------------------------------------------
#define SPLB   10240                  // bytes per matrix per split (128*40*2)
#define STAGEB (4*SPLB)               // 40960
#define NSTG   3
#define GSMEM  (NSTG*STAGEB)          // 122880

__global__ void __launch_bounds__(256)
gemm_mma(const bf16* __restrict__ Ah, const bf16* __restrict__ Al,
         const bf16* __restrict__ Bh, const bf16* __restrict__ Bl,
         const float* __restrict__ bias, float* __restrict__ C, int ldC)
{
    extern __shared__ char smc[];
    const uint32_t smb = smem_u32(smc);
    const int tid  = threadIdx.x;
    const int lane = tid & 31, wid = tid >> 5;
    const int wr   = wid >> 2, wc = wid & 3;
    const int row0 = blockIdx.y << 7, col0 = blockIdx.x << 7;

    const uint64_t gAh = gmem_u64(Ah), gAl = gmem_u64(Al);
    const uint64_t gBh = gmem_u64(Bh), gBl = gmem_u64(Bl);

    float acc[16][4];
    #pragma unroll
    for (int i = 0; i < 16; i++)
        #pragma unroll
        for (int j = 0; j < 4; j++) acc[i][j] = 0.f;

    // per-thread cp.async mapping: 512 16B-chunks per split, 2 per thread
    const int r0c = tid >> 1;                 // unused placeholder elimination
    (void)r0c;

    auto issue = [&](int c, int buf) {
        const uint32_t sb = smb + buf * STAGEB;
        #pragma unroll
        for (int i = 0; i < 2; i++) {
            const int id = tid + (i << 8);
            const int r = id >> 2, q = id & 3;
            const uint64_t ga = ((uint64_t)(row0 + r) * GK + (uint64_t)c * 32 + q * 8) * 2;
            const uint64_t gb = ((uint64_t)(col0 + r) * GK + (uint64_t)c * 32 + q * 8) * 2;
            const uint32_t so = r * 80 + q * 16;
            CP16(sb + so,            gAh + ga);
            CP16(sb + SPLB + so,     gAl + ga);
            CP16(sb + 2*SPLB + so,   gBh + gb);
            CP16(sb + 3*SPLB + so,   gBl + gb);
        }
        asm volatile("cp.async.commit_group;" ::: "memory");
    };

    issue(0, 0); issue(1, 1); issue(2, 2);

    const int lr = lane >> 2;            // 0..7
    const int lk = (lane & 3) << 1;      // 0,2,4,6

    #pragma unroll 1
    for (int c = 0; c < 128; c++) {
        if (c < 126)       asm volatile("cp.async.wait_group 2;" ::: "memory");
        else if (c == 126) asm volatile("cp.async.wait_group 1;" ::: "memory");
        else               asm volatile("cp.async.wait_group 0;" ::: "memory");
        __syncthreads();

        const char* sb  = smc + (c % NSTG) * STAGEB;
        const bf16* sAh = (const bf16*)(sb);
        const bf16* sAl = (const bf16*)(sb + SPLB);
        const bf16* sBh = (const bf16*)(sb + 2*SPLB);
        const bf16* sBl = (const bf16*)(sb + 3*SPLB);

        #pragma unroll
        for (int ks = 0; ks < 2; ks++) {
            const int kb = (ks << 4) + lk;
            uint32_t ahf[4][4], alf[4][4], bhf[4][2], blf[4][2];
            #pragma unroll
            for (int mi = 0; mi < 4; mi++) {
                const int r = wr * 64 + mi * 16 + lr;
                ahf[mi][0] = *(const uint32_t*)(sAh + r * 40 + kb);
                ahf[mi][1] = *(const uint32_t*)(sAh + (r + 8) * 40 + kb);
                ahf[mi][2] = *(const uint32_t*)(sAh + r * 40 + kb + 8);
                ahf[mi][3] = *(const uint32_t*)(sAh + (r + 8) * 40 + kb + 8);
                alf[mi][0] = *(const uint32_t*)(sAl + r * 40 + kb);
                alf[mi][1] = *(const uint32_t*)(sAl + (r + 8) * 40 + kb);
                alf[mi][2] = *(const uint32_t*)(sAl + r * 40 + kb + 8);
                alf[mi][3] = *(const uint32_t*)(sAl + (r + 8) * 40 + kb + 8);
            }
            #pragma unroll
            for (int ni = 0; ni < 4; ni++) {
                const int n = wc * 32 + ni * 8 + lr;
                bhf[ni][0] = *(const uint32_t*)(sBh + n * 40 + kb);
                bhf[ni][1] = *(const uint32_t*)(sBh + n * 40 + kb + 8);
                blf[ni][0] = *(const uint32_t*)(sBl + n * 40 + kb);
                blf[ni][1] = *(const uint32_t*)(sBl + n * 40 + kb + 8);
            }
            #pragma unroll
            for (int mi = 0; mi < 4; mi++)
                #pragma unroll
                for (int ni = 0; ni < 4; ni++) {
                    MMA16816(acc[mi * 4 + ni], ahf[mi], bhf[ni]);  // hi*hi
                    MMA16816(acc[mi * 4 + ni], ahf[mi], blf[ni]);  // hi*lo
                    MMA16816(acc[mi * 4 + ni], alf[mi], bhf[ni]);  // lo*hi
                }
        }
        __syncthreads();
        if (c + NSTG < 128) issue(c + NSTG, c % NSTG);
    }

    // epilogue
    #pragma unroll
    for (int mi = 0; mi < 4; mi++) {
        const int r = row0 + wr * 64 + mi * 16 + lr;
        #pragma unroll
        for (int ni = 0; ni < 4; ni++) {
            const int cc = col0 + wc * 32 + ni * 8 + lk;
            float b0 = 0.f, b1 = 0.f;
            if (bias) { b0 = __ldg(bias + cc); b1 = __ldg(bias + cc + 1); }
            float* p0 = C + (size_t)r * ldC + cc;
            float* p1 = C + (size_t)(r + 8) * ldC + cc;
            p0[0] = acc[mi * 4 + ni][0] + b0;
            p0[1] = acc[mi * 4 + ni][1] + b1;
            p1[0] = acc[mi * 4 + ni][2] + b0;
            p1[1] = acc[mi * 4 + ni][3] + b1;
        }
    }
}

// ---------------------------------------------------------------------------
// RoPE (in place, float4): x rows at rowstride floats, head h at offset h*HD.
// ---------------------------------------------------------------------------
__global__ void rope_kernel(float* __restrict__ x, const float* __restrict__ cs,
                            const float* __restrict__ sn, int nheads, int rowstride, int total)
{
    int p = blockIdx.x * blockDim.x + threadIdx.x;
    if (p >= total) return;
    const int d    = (p & 15) << 2;
    const int h    = (p >> 4) % nheads;
    const int sidx = p / (16 * nheads);
    float* base = x + (size_t)sidx * rowstride + h * HDC;
    const float* cb = cs + (size_t)sidx * HDC;
    const float* sb = sn + (size_t)sidx * HDC;
    const float4 x1 = *(const float4*)(base + d);
    const float4 x2 = *(const float4*)(base + d + 64);
    const float4 c1 = *(const float4*)(cb + d),      s1 = *(const float4*)(sb + d);
    const float4 c2 = *(const float4*)(cb + d + 64), s2 = *(const float4*)(sb + d + 64);
    float4 o1, o2;
    o1.x = x1.x * c1.x - x2.x * s1.x;  o1.y = x1.y * c1.y - x2.y * s1.y;
    o1.z = x1.z * c1.z - x2.z * s1.z;  o1.w = x1.w * c1.w - x2.w * s1.w;
    o2.x = x2.x * c2.x + x1.x * s2.x;  o2.y = x2.y * c2.y + x1.y * s2.y;
    o2.z = x2.z * c2.z + x1.z * s2.z;  o2.w = x2.w * c2.w + x1.w * s2.w;
    *(float4*)(base + d)      = o1;
    *(float4*)(base + d + 64) = o2;
}

// ---------------------------------------------------------------------------
// Flash attention (fp32): per (b, h, 64-row q-tile). KV packed [row][K|V].
// ---------------------------------------------------------------------------
#define LDT 132
#define LDP 68
#define ATTN_SMEM ((2 * 64 * LDT + 64 * LDP) * 4)

__global__ void __launch_bounds__(256, 2)
attn_kernel(const float* __restrict__ Q, const float* __restrict__ KV,
            float* __restrict__ O)
{
    extern __shared__ float smf[];
    float* Qs  = smf;
    float* KVs = smf + 64 * LDT;
    float* P   = smf + 2 * 64 * LDT;

    const int tid = threadIdx.x;
    const int qt  = blockIdx.x;
    const int h   = blockIdx.y;
    const int b   = blockIdx.z;
    const int kvh = h >> 2;
    const int r   = tid >> 2;
    const int c4  = tid & 3;
    const float scale = 0.08838834764831845f;

    const float* qb = Q + ((size_t)(b * SS + qt * 64) * NHC + h) * HDC;
    #pragma unroll
    for (int i = 0; i < 8; i++) {
        const int s = tid + (i << 8);
        const int row = s >> 5, d4 = s & 31;
        *(float4*)(Qs + row * LDT + (d4 << 2)) =
            *(const float4*)(qb + (size_t)row * (NHC * HDC) + (d4 << 2));
    }

    float  m = -INFINITY, l = 0.f;
    float4 oacc[8];
    #pragma unroll
    for (int i = 0; i < 8; i++) oacc[i] = make_float4(0.f, 0.f, 0.f, 0.f);

    const float* kbase0 = KV + (size_t)(b * SS) * KVW + kvh * HDC;
    const float* vbase0 = kbase0 + NKVC * HDC;

    for (int kt = 0; kt < SS / 64; kt++) {
        __syncthreads();
        {
            const float* kb = kbase0 + (size_t)kt * 64 * KVW;
            #pragma unroll
            for (int i = 0; i < 8; i++) {
                const int s = tid + (i << 8);
                const int row = s >> 5, d4 = s & 31;
                *(float4*)(KVs + row * LDT + (d4 << 2)) =
                    *(const float4*)(kb + (size_t)row * KVW + (d4 << 2));
            }
        }
        __syncthreads();

        float sc[16];
        #pragma unroll
        for (int jj = 0; jj < 16; jj++) sc[jj] = 0.f;
        const float4* qrow = (const float4*)(Qs + r * LDT);
        #pragma unroll 4
        for (int d4 = 0; d4 < 32; d4++) {
            const float4 q4 = qrow[d4];
            #pragma unroll
            for (int jj = 0; jj < 16; jj++) {
                const float4 k4 = *((const float4*)(KVs + (jj * 4 + c4) * LDT) + d4);
                sc[jj] = fmaf(q4.x, k4.x, fmaf(q4.y, k4.y,
                         fmaf(q4.z, k4.z, fmaf(q4.w, k4.w, sc[jj]))));
            }
        }

        float tmax = -INFINITY;
        #pragma unroll
        for (int jj = 0; jj < 16; jj++) { sc[jj] *= scale; tmax = fmaxf(tmax, sc[jj]); }
        tmax = fmaxf(tmax, __shfl_xor_sync(0xffffffffu, tmax, 1));
        tmax = fmaxf(tmax, __shfl_xor_sync(0xffffffffu, tmax, 2));
        const float mnew = fmaxf(m, tmax);
        const float corr = __expf(m - mnew);
        float lsum = 0.f;
        #pragma unroll
        for (int jj = 0; jj < 16; jj++) {
            const float e = __expf(sc[jj] - mnew);
            P[r * LDP + jj * 4 + c4] = e;
            lsum += e;
        }
        lsum += __shfl_xor_sync(0xffffffffu, lsum, 1);
        lsum += __shfl_xor_sync(0xffffffffu, lsum, 2);
        l = l * corr + lsum;
        m = mnew;
        #pragma unroll
        for (int i = 0; i < 8; i++) {
            oacc[i].x *= corr; oacc[i].y *= corr;
            oacc[i].z *= corr; oacc[i].w *= corr;
        }

        __syncthreads();
        {
            const float* vb = vbase0 + (size_t)kt * 64 * KVW;
            #pragma unroll
            for (int i = 0; i < 8; i++) {
                const int s = tid + (i << 8);
                const int row = s >> 5, d4 = s & 31;
                *(float4*)(KVs + row * LDT + (d4 << 2)) =
                    *(const float4*)(vb + (size_t)row * KVW + (d4 << 2));
            }
        }
        __syncthreads();

        #pragma unroll 2
        for (int j = 0; j < 64; j++) {
            const float p = P[r * LDP + j];
            const float4* vr = (const float4*)(KVs + j * LDT);
            #pragma unroll
            for (int cc = 0; cc < 8; cc++) {
                const float4 v4 = vr[c4 + cc * 4];
                oacc[cc].x = fmaf(p, v4.x, oacc[cc].x);
                oacc[cc].y = fmaf(p, v4.y, oacc[cc].y);
                oacc[cc].z = fmaf(p, v4.z, oacc[cc].z);
                oacc[cc].w = fmaf(p, v4.w, oacc[cc].w);
            }
        }
    }

    const float inv = 1.f / l;
    float* ob = O + ((size_t)(b * SS + qt * 64 + r) * NHC + h) * HDC;
    #pragma unroll
    for (int cc = 0; cc < 8; cc++) {
        float4 v = oacc[cc];
        v.x *= inv; v.y *= inv; v.z *= inv; v.w *= inv;
        *(float4*)(ob + ((c4 + cc * 4) << 2)) = v;
    }
}

// ---------------------------------------------------------------------------
// Launch
// ---------------------------------------------------------------------------
extern "C" void kernel_launch(void* const* d_in, const int* in_sizes, int n_in,
                              void* d_out, int out_size)
{
    (void)in_sizes; (void)n_in; (void)out_size;
    const float* hidden = (const float*)d_in[0];
    const float* cosp   = (const float*)d_in[1];
    const float* sinp   = (const float*)d_in[2];
    const float* Wq     = (const float*)d_in[3];
    const float* bq     = (const float*)d_in[4];
    const float* Wk     = (const float*)d_in[5];
    const float* bk     = (const float*)d_in[6];
    const float* Wv     = (const float*)d_in[7];
    const float* bv     = (const float*)d_in[8];
    const float* Wo     = (const float*)d_in[9];
    float* out = (float*)d_out;

    bf16 *ah, *al, *wqh, *wql, *wkh, *wkl, *wvh, *wvl, *woh, *wol, *oth, *otl;
    float *q, *kv, *att;
    cudaGetSymbolAddress((void**)&ah,  g_ah);
    cudaGetSymbolAddress((void**)&al,  g_al);
    cudaGetSymbolAddress((void**)&wqh, g_wqh);
    cudaGetSymbolAddress((void**)&wql, g_wql);
    cudaGetSymbolAddress((void**)&wkh, g_wkh);
    cudaGetSymbolAddress((void**)&wkl, g_wkl);
    cudaGetSymbolAddress((void**)&wvh, g_wvh);
    cudaGetSymbolAddress((void**)&wvl, g_wvl);
    cudaGetSymbolAddress((void**)&woh, g_woh);
    cudaGetSymbolAddress((void**)&wol, g_wol);
    cudaGetSymbolAddress((void**)&oth, g_oth);
    cudaGetSymbolAddress((void**)&otl, g_otl);
    cudaGetSymbolAddress((void**)&q,   g_q);
    cudaGetSymbolAddress((void**)&kv,  g_kv);
    cudaGetSymbolAddress((void**)&att, g_att);

    cudaFuncSetAttribute(gemm_mma,
                         cudaFuncAttributeMaxDynamicSharedMemorySize, GSMEM);
    cudaFuncSetAttribute(attn_kernel,
                         cudaFuncAttributeMaxDynamicSharedMemorySize, ATTN_SMEM);

    const dim3 tb(32, 8);
    // pre-passes: activation split + weight split-transpose
    {
        const int n4 = MROWS * HIDC / 4;
        split_kernel<<<(n4 + 255) / 256, 256>>>(hidden, ah, al, n4);
    }
    wsplitT_kernel<<<dim3(HIDC / 32, GK / 32), tb>>>(Wq, wqh, wql, HIDC);
    wsplitT_kernel<<<dim3((NKVC * HDC) / 32, GK / 32), tb>>>(Wk, wkh, wkl, NKVC * HDC);
    wsplitT_kernel<<<dim3((NKVC * HDC) / 32, GK / 32), tb>>>(Wv, wvh, wvl, NKVC * HDC);
    wsplitT_kernel<<<dim3(HIDC / 32, GK / 32), tb>>>(Wo, woh, wol, HIDC);

    // projections (tensor path)
    gemm_mma<<<dim3(HIDC / 128, MROWS / 128), 256, GSMEM>>>(ah, al, wqh, wql, bq, q, HIDC);
    gemm_mma<<<dim3((NKVC * HDC) / 128, MROWS / 128), 256, GSMEM>>>(ah, al, wkh, wkl, bk, kv, KVW);
    gemm_mma<<<dim3((NKVC * HDC) / 128, MROWS / 128), 256, GSMEM>>>(ah, al, wvh, wvl, bv, kv + NKVC * HDC, KVW);

    // RoPE on q and k-part of kv
    const int tq = MROWS * NHC * 16;
    rope_kernel<<<(tq + 255) / 256, 256>>>(q, cosp, sinp, NHC, NHC * HDC, tq);
    const int tk = MROWS * NKVC * 16;
    rope_kernel<<<(tk + 255) / 256, 256>>>(kv, cosp, sinp, NKVC, KVW, tk);

    // attention (fp32)
    attn_kernel<<<dim3(SS / 64, NHC, BB), 256, ATTN_SMEM>>>(q, kv, att);

    // split att, then output projection
    {
        const int n4 = MROWS * HIDC / 4;
        split_kernel<<<(n4 + 255) / 256, 256>>>(att, oth, otl, n4);
    }
    gemm_mma<<<dim3(HIDC / 128, MROWS / 128), 256, GSMEM>>>(oth, otl, woh, wol, nullptr, out, HIDC);
}

// round 10
// speedup vs baseline: 3.1269x; 2.4480x over previous
#include <cuda_runtime.h>
#include <cuda_bf16.h>
#include <stdint.h>
#include <math.h>

// Problem constants
#define BB      2
#define SS      2048
#define HIDC    4096
#define NHC     32
#define NKVC    8
#define HDC     128
#define MROWS   (BB*SS)          // 4096
#define KVW     (2*NKVC*HDC)     // 2048 combined K|V row width
#define GK      4096             // reduction dim for every projection

typedef __nv_bfloat16 bf16;

// ---------------------------------------------------------------------------
// Scratch (device globals: the sanctioned alloc-free scratch path)
// ---------------------------------------------------------------------------
__device__ bf16  g_ah [(size_t)MROWS * HIDC];   // hidden hi
__device__ bf16  g_al [(size_t)MROWS * HIDC];   // hidden lo
__device__ bf16  g_wqh[(size_t)HIDC * GK];      // Wq^T hi [N][K]
__device__ bf16  g_wql[(size_t)HIDC * GK];
__device__ bf16  g_wkh[(size_t)(NKVC*HDC) * GK];
__device__ bf16  g_wkl[(size_t)(NKVC*HDC) * GK];
__device__ bf16  g_wvh[(size_t)(NKVC*HDC) * GK];
__device__ bf16  g_wvl[(size_t)(NKVC*HDC) * GK];
__device__ bf16  g_woh[(size_t)HIDC * GK];
__device__ bf16  g_wol[(size_t)HIDC * GK];
__device__ bf16  g_oth[(size_t)MROWS * HIDC];   // att hi (written by attn)
__device__ bf16  g_otl[(size_t)MROWS * HIDC];   // att lo
__device__ float g_q  [(size_t)MROWS * HIDC];
__device__ float g_kv [(size_t)MROWS * KVW];    // [row][K(1024)|V(1024)]

// ---------------------------------------------------------------------------
// small helpers
// ---------------------------------------------------------------------------
__device__ __forceinline__ uint64_t gmem_u64(const void* p) {
    uint64_t a;
    asm("cvta.to.global.u64 %0, %1;" : "=l"(a) : "l"(p));
    return a;
}
#define CP16(smaddr, gaddr) \
    asm volatile("cp.async.cg.shared.global [%0], [%1], 16;" :: "r"(smaddr), "l"(gaddr) : "memory")
__device__ __forceinline__ uint32_t smem_u32(const void* p) {
    uint32_t a;
    asm("{ .reg .u64 t; cvta.to.shared.u64 t, %1; cvt.u32.u64 %0, t; }" : "=r"(a) : "l"(p));
    return a;
}

#define MMA16816(d, a, b) \
    asm volatile("mma.sync.aligned.m16n8k16.row.col.f32.bf16.bf16.f32 " \
        "{%0,%1,%2,%3}, {%4,%5,%6,%7}, {%8,%9}, {%0,%1,%2,%3};" \
        : "+f"((d)[0]), "+f"((d)[1]), "+f"((d)[2]), "+f"((d)[3]) \
        : "r"((a)[0]), "r"((a)[1]), "r"((a)[2]), "r"((a)[3]), \
          "r"((b)[0]), "r"((b)[1]))

// ---------------------------------------------------------------------------
// Pre-pass: split fp32 -> (hi, lo) bf16, same layout.  n4 = elems/4
// ---------------------------------------------------------------------------
__global__ void split_kernel(const float* __restrict__ x, bf16* __restrict__ h,
                             bf16* __restrict__ l, int n4)
{
    int i = blockIdx.x * blockDim.x + threadIdx.x;
    if (i >= n4) return;
    const float4 v = ((const float4*)x)[i];
    bf16 h0 = __float2bfloat16(v.x), h1 = __float2bfloat16(v.y);
    bf16 h2 = __float2bfloat16(v.z), h3 = __float2bfloat16(v.w);
    bf16 l0 = __float2bfloat16(v.x - __bfloat162float(h0));
    bf16 l1 = __float2bfloat16(v.y - __bfloat162float(h1));
    bf16 l2 = __float2bfloat16(v.z - __bfloat162float(h2));
    bf16 l3 = __float2bfloat16(v.w - __bfloat162float(h3));
    ((__nv_bfloat162*)h)[2*i]     = __halves2bfloat162(h0, h1);
    ((__nv_bfloat162*)h)[2*i + 1] = __halves2bfloat162(h2, h3);
    ((__nv_bfloat162*)l)[2*i]     = __halves2bfloat162(l0, l1);
    ((__nv_bfloat162*)l)[2*i + 1] = __halves2bfloat162(l2, l3);
}

// ---------------------------------------------------------------------------
// Pre-pass: W[k][n] fp32 -> Wt_hi/Wt_lo [n][k] bf16  (K = GK rows)
// ---------------------------------------------------------------------------
__global__ void wsplitT_kernel(const float* __restrict__ W, bf16* __restrict__ th,
                               bf16* __restrict__ tl, int Ncols)
{
    __shared__ float t[32][33];
    const int bx = blockIdx.x * 32, by = blockIdx.y * 32;
    const int tx = threadIdx.x, ty = threadIdx.y;
    #pragma unroll
    for (int i = 0; i < 4; i++)
        t[ty + i * 8][tx] = W[(size_t)(by + ty + i * 8) * Ncols + bx + tx];
    __syncthreads();
    #pragma unroll
    for (int i = 0; i < 4; i++) {
        const float v = t[tx][ty + i * 8];
        const size_t o = (size_t)(bx + ty + i * 8) * GK + by + tx;
        const bf16 h = __float2bfloat16(v);
        th[o] = h;
        tl[o] = __float2bfloat16(v - __bfloat162float(h));
    }
}

// ---------------------------------------------------------------------------
// 3x bf16-split GEMM via mma.sync. C[M][N] = A[M][GK] @ Bt[N][GK]^T (+bias).
// CTA tile 128x128, BK=32, 8 warps (2x4) of 64x32, 2-stage cp.async pipeline,
// 2 CTAs/SM (__launch_bounds__(256,2)).
// ---------------------------------------------------------------------------
#define SPLB   10240                  // 128 rows * 40 bf16 * 2B
#define STAGEB (4*SPLB)               // 40960
#define NSTG   2
#define GSMEM  (NSTG*STAGEB)          // 81920

__global__ void __launch_bounds__(256, 2)
gemm_mma(const bf16* __restrict__ Ah, const bf16* __restrict__ Al,
         const bf16* __restrict__ Bh, const bf16* __restrict__ Bl,
         const float* __restrict__ bias, float* __restrict__ C, int ldC)
{
    extern __shared__ char smc[];
    const uint32_t smb = smem_u32(smc);
    const int tid  = threadIdx.x;
    const int lane = tid & 31, wid = tid >> 5;
    const int wr   = wid >> 2, wc = wid & 3;
    const int row0 = blockIdx.y << 7, col0 = blockIdx.x << 7;

    const uint64_t gAh = gmem_u64(Ah), gAl = gmem_u64(Al);
    const uint64_t gBh = gmem_u64(Bh), gBl = gmem_u64(Bl);

    float acc[16][4];
    #pragma unroll
    for (int i = 0; i < 16; i++)
        #pragma unroll
        for (int j = 0; j < 4; j++) acc[i][j] = 0.f;

    auto issue = [&](int c, int buf) {
        const uint32_t sb = smb + buf * STAGEB;
        #pragma unroll
        for (int i = 0; i < 2; i++) {
            const int id = tid + (i << 8);
            const int r = id >> 2, q = id & 3;
            const uint64_t ga = ((uint64_t)(row0 + r) * GK + (uint64_t)c * 32 + q * 8) * 2;
            const uint64_t gb = ((uint64_t)(col0 + r) * GK + (uint64_t)c * 32 + q * 8) * 2;
            const uint32_t so = r * 80 + q * 16;
            CP16(sb + so,            gAh + ga);
            CP16(sb + SPLB + so,     gAl + ga);
            CP16(sb + 2*SPLB + so,   gBh + gb);
            CP16(sb + 3*SPLB + so,   gBl + gb);
        }
        asm volatile("cp.async.commit_group;" ::: "memory");
    };

    issue(0, 0); issue(1, 1);

    const int lr = lane >> 2;            // 0..7
    const int lk = (lane & 3) << 1;      // 0,2,4,6

    #pragma unroll 1
    for (int c = 0; c < 128; c++) {
        if (c < 127) asm volatile("cp.async.wait_group 1;" ::: "memory");
        else         asm volatile("cp.async.wait_group 0;" ::: "memory");
        __syncthreads();

        const char* sb  = smc + (c & 1) * STAGEB;
        const bf16* sAh = (const bf16*)(sb);
        const bf16* sAl = (const bf16*)(sb + SPLB);
        const bf16* sBh = (const bf16*)(sb + 2*SPLB);
        const bf16* sBl = (const bf16*)(sb + 3*SPLB);

        #pragma unroll
        for (int ks = 0; ks < 2; ks++) {
            const int kb = (ks << 4) + lk;
            uint32_t bhf[4][2], blf[4][2];
            #pragma unroll
            for (int ni = 0; ni < 4; ni++) {
                const int n = wc * 32 + ni * 8 + lr;
                bhf[ni][0] = *(const uint32_t*)(sBh + n * 40 + kb);
                bhf[ni][1] = *(const uint32_t*)(sBh + n * 40 + kb + 8);
                blf[ni][0] = *(const uint32_t*)(sBl + n * 40 + kb);
                blf[ni][1] = *(const uint32_t*)(sBl + n * 40 + kb + 8);
            }
            #pragma unroll
            for (int mi = 0; mi < 4; mi++) {
                const int r = wr * 64 + mi * 16 + lr;
                uint32_t ahf[4], alf[4];
                ahf[0] = *(const uint32_t*)(sAh + r * 40 + kb);
                ahf[1] = *(const uint32_t*)(sAh + (r + 8) * 40 + kb);
                ahf[2] = *(const uint32_t*)(sAh + r * 40 + kb + 8);
                ahf[3] = *(const uint32_t*)(sAh + (r + 8) * 40 + kb + 8);
                alf[0] = *(const uint32_t*)(sAl + r * 40 + kb);
                alf[1] = *(const uint32_t*)(sAl + (r + 8) * 40 + kb);
                alf[2] = *(const uint32_t*)(sAl + r * 40 + kb + 8);
                alf[3] = *(const uint32_t*)(sAl + (r + 8) * 40 + kb + 8);
                #pragma unroll
                for (int ni = 0; ni < 4; ni++) {
                    MMA16816(acc[mi * 4 + ni], ahf, bhf[ni]);
                    MMA16816(acc[mi * 4 + ni], ahf, blf[ni]);
                    MMA16816(acc[mi * 4 + ni], alf, bhf[ni]);
                }
            }
        }
        __syncthreads();
        if (c + NSTG < 128) issue(c + NSTG, c & 1);
    }

    // epilogue
    #pragma unroll
    for (int mi = 0; mi < 4; mi++) {
        const int r = row0 + wr * 64 + mi * 16 + lr;
        #pragma unroll
        for (int ni = 0; ni < 4; ni++) {
            const int cc = col0 + wc * 32 + ni * 8 + lk;
            float b0 = 0.f, b1 = 0.f;
            if (bias) { b0 = __ldg(bias + cc); b1 = __ldg(bias + cc + 1); }
            float* p0 = C + (size_t)r * ldC + cc;
            float* p1 = C + (size_t)(r + 8) * ldC + cc;
            p0[0] = acc[mi * 4 + ni][0] + b0;
            p0[1] = acc[mi * 4 + ni][1] + b1;
            p1[0] = acc[mi * 4 + ni][2] + b0;
            p1[1] = acc[mi * 4 + ni][3] + b1;
        }
    }
}

// ---------------------------------------------------------------------------
// RoPE (in place, float4)
// ---------------------------------------------------------------------------
__global__ void rope_kernel(float* __restrict__ x, const float* __restrict__ cs,
                            const float* __restrict__ sn, int nheads, int rowstride, int total)
{
    int p = blockIdx.x * blockDim.x + threadIdx.x;
    if (p >= total) return;
    const int d    = (p & 15) << 2;
    const int h    = (p >> 4) % nheads;
    const int sidx = p / (16 * nheads);
    float* base = x + (size_t)sidx * rowstride + h * HDC;
    const float* cb = cs + (size_t)sidx * HDC;
    const float* sb = sn + (size_t)sidx * HDC;
    const float4 x1 = *(const float4*)(base + d);
    const float4 x2 = *(const float4*)(base + d + 64);
    const float4 c1 = *(const float4*)(cb + d),      s1 = *(const float4*)(sb + d);
    const float4 c2 = *(const float4*)(cb + d + 64), s2 = *(const float4*)(sb + d + 64);
    float4 o1, o2;
    o1.x = x1.x * c1.x - x2.x * s1.x;  o1.y = x1.y * c1.y - x2.y * s1.y;
    o1.z = x1.z * c1.z - x2.z * s1.z;  o1.w = x1.w * c1.w - x2.w * s1.w;
    o2.x = x2.x * c2.x + x1.x * s2.x;  o2.y = x2.y * c2.y + x1.y * s2.y;
    o2.z = x2.z * c2.z + x1.z * s2.z;  o2.w = x2.w * c2.w + x1.w * s2.w;
    *(float4*)(base + d)      = o1;
    *(float4*)(base + d + 64) = o2;
}

// ---------------------------------------------------------------------------
// Flash attention on mma.sync bf16 with hi/lo split (3-term).
// Br=128 q-rows per CTA, Bc=64 keys per tile, 8 warps (4 row-groups x 2 col).
// Q/K staged fp32->split bf16; P split to smem; V staged transposed [d][kv].
// Writes output directly as (hi,lo) bf16 for the O-projection GEMM.
// ---------------------------------------------------------------------------
#define ALD    136          // Q/K smem row stride (bf16 elems)
#define PLD    72           // P and Vt smem row stride
#define OFF_QL (128*ALD*2)              // 34816
#define OFF_KA (2*128*ALD*2)            // 69632
#define OFF_KB (OFF_KA + 18432)         // 88064
#define OFF_PH (OFF_KB + 18432)         // 106496
#define OFF_PL (OFF_PH + 128*PLD*2)     // 124928
#define OFF_MX (OFF_PL + 128*PLD*2)     // 143360
#define OFF_SM (OFF_MX + 1024)          // 144384
#define ATTN_SMEM (OFF_SM + 1024)       // 145408
#define SCALE 0.08838834764831845f

__device__ __forceinline__ void split_st4(float4 v, bf16* dh, bf16* dl) {
    bf16 h0 = __float2bfloat16(v.x), h1 = __float2bfloat16(v.y);
    bf16 h2 = __float2bfloat16(v.z), h3 = __float2bfloat16(v.w);
    ((__nv_bfloat162*)dh)[0] = __halves2bfloat162(h0, h1);
    ((__nv_bfloat162*)dh)[1] = __halves2bfloat162(h2, h3);
    ((__nv_bfloat162*)dl)[0] = __halves2bfloat162(
        __float2bfloat16(v.x - __bfloat162float(h0)),
        __float2bfloat16(v.y - __bfloat162float(h1)));
    ((__nv_bfloat162*)dl)[1] = __halves2bfloat162(
        __float2bfloat16(v.z - __bfloat162float(h2)),
        __float2bfloat16(v.w - __bfloat162float(h3)));
}

__global__ void __launch_bounds__(256, 1)
attn_mma(const float* __restrict__ Q, const float* __restrict__ KV,
         bf16* __restrict__ Oh, bf16* __restrict__ Ol)
{
    extern __shared__ char sm[];
    bf16*  sQh = (bf16*)(sm);
    bf16*  sQl = (bf16*)(sm + OFF_QL);
    bf16*  sKh = (bf16*)(sm + OFF_KA);    // union: K hi | Vt hi
    bf16*  sKl = (bf16*)(sm + OFF_KB);    // union: K lo | Vt lo
    bf16*  sPh = (bf16*)(sm + OFF_PH);
    bf16*  sPl = (bf16*)(sm + OFF_PL);
    float* sMax = (float*)(sm + OFF_MX);
    float* sSum = (float*)(sm + OFF_SM);

    const int tid = threadIdx.x, lane = tid & 31, wid = tid >> 5;
    const int wr = wid >> 1, wc = wid & 1;
    const int lr = lane >> 2, lq = lane & 3;
    const int qt = blockIdx.x, head = blockIdx.y, b = blockIdx.z;
    const int kvh = head >> 2;

    // ---- stage Q tile (128 x 128), pre-scaled + split ----
    {
        const float* qb = Q + ((size_t)(b * SS + qt * 128) * NHC + head) * HDC;
        #pragma unroll
        for (int i = 0; i < 16; i++) {
            const int id = tid + (i << 8);
            const int row = id >> 5, d0 = (id & 31) << 2;
            float4 v = *(const float4*)(qb + (size_t)row * (NHC * HDC) + d0);
            v.x *= SCALE; v.y *= SCALE; v.z *= SCALE; v.w *= SCALE;
            split_st4(v, sQh + row * ALD + d0, sQl + row * ALD + d0);
        }
    }

    float m[2][2], l[2][2];
    #pragma unroll
    for (int i = 0; i < 2; i++)
        #pragma unroll
        for (int j = 0; j < 2; j++) { m[i][j] = -INFINITY; l[i][j] = 0.f; }
    float oacc[2][8][4];
    #pragma unroll
    for (int a = 0; a < 2; a++)
        #pragma unroll
        for (int n = 0; n < 8; n++)
            #pragma unroll
            for (int r = 0; r < 4; r++) oacc[a][n][r] = 0.f;

    #pragma unroll 1
    for (int kt = 0; kt < SS / 64; kt++) {
        __syncthreads();   // prev PV done with Vt / P / reductions

        // ---- stage K tile (64 x 128) split ----
        {
            const float* kb = KV + (size_t)(b * SS + kt * 64) * KVW + kvh * HDC;
            #pragma unroll
            for (int i = 0; i < 8; i++) {
                const int id = tid + (i << 8);
                const int row = id >> 5, d0 = (id & 31) << 2;
                float4 v = *(const float4*)(kb + (size_t)row * KVW + d0);
                split_st4(v, sKh + row * ALD + d0, sKl + row * ALD + d0);
            }
        }
        __syncthreads();

        // ---- scores: 3-term split MMA, acc fp32 ----
        float sc[2][4][4];
        #pragma unroll
        for (int a = 0; a < 2; a++)
            #pragma unroll
            for (int n = 0; n < 4; n++)
                #pragma unroll
                for (int r = 0; r < 4; r++) sc[a][n][r] = 0.f;

        #pragma unroll
        for (int ks = 0; ks < 8; ks++) {
            const int k0 = (ks << 4) + (lq << 1);
            uint32_t bh[4][2], bl[4][2];
            #pragma unroll
            for (int ni = 0; ni < 4; ni++) {
                const int n = wc * 32 + ni * 8 + lr;
                bh[ni][0] = *(const uint32_t*)(sKh + n * ALD + k0);
                bh[ni][1] = *(const uint32_t*)(sKh + n * ALD + k0 + 8);
                bl[ni][0] = *(const uint32_t*)(sKl + n * ALD + k0);
                bl[ni][1] = *(const uint32_t*)(sKl + n * ALD + k0 + 8);
            }
            #pragma unroll
            for (int mi = 0; mi < 2; mi++) {
                const int r = wr * 32 + mi * 16 + lr;
                uint32_t ah[4], al[4];
                ah[0] = *(const uint32_t*)(sQh + r * ALD + k0);
                ah[1] = *(const uint32_t*)(sQh + (r + 8) * ALD + k0);
                ah[2] = *(const uint32_t*)(sQh + r * ALD + k0 + 8);
                ah[3] = *(const uint32_t*)(sQh + (r + 8) * ALD + k0 + 8);
                al[0] = *(const uint32_t*)(sQl + r * ALD + k0);
                al[1] = *(const uint32_t*)(sQl + (r + 8) * ALD + k0);
                al[2] = *(const uint32_t*)(sQl + r * ALD + k0 + 8);
                al[3] = *(const uint32_t*)(sQl + (r + 8) * ALD + k0 + 8);
                #pragma unroll
                for (int ni = 0; ni < 4; ni++) {
                    MMA16816(sc[mi][ni], ah, bh[ni]);
                    MMA16816(sc[mi][ni], ah, bl[ni]);
                    MMA16816(sc[mi][ni], al, bh[ni]);
                }
            }
        }

        // ---- online softmax: tile row-max ----
        #pragma unroll
        for (int mi = 0; mi < 2; mi++)
            #pragma unroll
            for (int hf = 0; hf < 2; hf++) {
                float mx = -INFINITY;
                #pragma unroll
                for (int ni = 0; ni < 4; ni++)
                    mx = fmaxf(mx, fmaxf(sc[mi][ni][2*hf], sc[mi][ni][2*hf+1]));
                mx = fmaxf(mx, __shfl_xor_sync(0xffffffffu, mx, 1));
                mx = fmaxf(mx, __shfl_xor_sync(0xffffffffu, mx, 2));
                if (lq == 0)
                    sMax[(wr * 32 + mi * 16 + lr + 8 * hf) * 2 + wc] = mx;
            }
        __syncthreads();

        float corr[2][2];
        #pragma unroll
        for (int mi = 0; mi < 2; mi++)
            #pragma unroll
            for (int hf = 0; hf < 2; hf++) {
                const int row = wr * 32 + mi * 16 + lr + 8 * hf;
                const float tmax = fmaxf(sMax[row * 2], sMax[row * 2 + 1]);
                const float mnew = fmaxf(m[mi][hf], tmax);
                corr[mi][hf] = __expf(m[mi][hf] - mnew);
                m[mi][hf] = mnew;
                float rs = 0.f;
                #pragma unroll
                for (int ni = 0; ni < 4; ni++) {
                    const float e0 = __expf(sc[mi][ni][2*hf]   - mnew);
                    const float e1 = __expf(sc[mi][ni][2*hf+1] - mnew);
                    rs += e0 + e1;
                    const bf16 h0 = __float2bfloat16(e0);
                    const bf16 h1 = __float2bfloat16(e1);
                    const int cc = wc * 32 + ni * 8 + (lq << 1);
                    *(__nv_bfloat162*)(sPh + row * PLD + cc) = __halves2bfloat162(h0, h1);
                    *(__nv_bfloat162*)(sPl + row * PLD + cc) = __halves2bfloat162(
                        __float2bfloat16(e0 - __bfloat162float(h0)),
                        __float2bfloat16(e1 - __bfloat162float(h1)));
                }
                rs += __shfl_xor_sync(0xffffffffu, rs, 1);
                rs += __shfl_xor_sync(0xffffffffu, rs, 2);
                if (lq == 0) sSum[row * 2 + wc] = rs;
                #pragma unroll
                for (int ni = 0; ni < 8; ni++) {
                    oacc[mi][ni][2*hf]   *= corr[mi][hf];
                    oacc[mi][ni][2*hf+1] *= corr[mi][hf];
                }
            }

        // ---- stage V transposed: sVt[d][kv] (reuses K buffers) ----
        {
            const int kv0  = (tid & 31) * 2;
            const int dblk = (tid >> 5) * 16;
            const float* vb = KV + (size_t)(b * SS + kt * 64 + kv0) * KVW
                             + NKVC * HDC + kvh * HDC + dblk;
            #pragma unroll
            for (int j = 0; j < 4; j++) {
                const float4 v0 = *(const float4*)(vb + j * 4);
                const float4 v1 = *(const float4*)(vb + KVW + j * 4);
                const float e0[4] = {v0.x, v0.y, v0.z, v0.w};
                const float e1[4] = {v1.x, v1.y, v1.z, v1.w};
                #pragma unroll
                for (int e = 0; e < 4; e++) {
                    const int d = dblk + j * 4 + e;
                    const bf16 a0 = __float2bfloat16(e0[e]);
                    const bf16 a1 = __float2bfloat16(e1[e]);
                    *(__nv_bfloat162*)(sKh + d * PLD + kv0) = __halves2bfloat162(a0, a1);
                    *(__nv_bfloat162*)(sKl + d * PLD + kv0) = __halves2bfloat162(
                        __float2bfloat16(e0[e] - __bfloat162float(a0)),
                        __float2bfloat16(e1[e] - __bfloat162float(a1)));
                }
            }
        }
        __syncthreads();

        // ---- l update ----
        #pragma unroll
        for (int mi = 0; mi < 2; mi++)
            #pragma unroll
            for (int hf = 0; hf < 2; hf++) {
                const int row = wr * 32 + mi * 16 + lr + 8 * hf;
                l[mi][hf] = l[mi][hf] * corr[mi][hf] + sSum[row * 2] + sSum[row * 2 + 1];
            }

        // ---- PV: 3-term split MMA ----
        #pragma unroll
        for (int ks = 0; ks < 4; ks++) {
            const int k0 = (ks << 4) + (lq << 1);
            #pragma unroll
            for (int mi = 0; mi < 2; mi++) {
                const int r = wr * 32 + mi * 16 + lr;
                uint32_t ph[4], pl[4];
                ph[0] = *(const uint32_t*)(sPh + r * PLD + k0);
                ph[1] = *(const uint32_t*)(sPh + (r + 8) * PLD + k0);
                ph[2] = *(const uint32_t*)(sPh + r * PLD + k0 + 8);
                ph[3] = *(const uint32_t*)(sPh + (r + 8) * PLD + k0 + 8);
                pl[0] = *(const uint32_t*)(sPl + r * PLD + k0);
                pl[1] = *(const uint32_t*)(sPl + (r + 8) * PLD + k0);
                pl[2] = *(const uint32_t*)(sPl + r * PLD + k0 + 8);
                pl[3] = *(const uint32_t*)(sPl + (r + 8) * PLD + k0 + 8);
                #pragma unroll
                for (int ni = 0; ni < 8; ni++) {
                    const int n = wc * 64 + ni * 8 + lr;
                    uint32_t vh[2], vl[2];
                    vh[0] = *(const uint32_t*)(sKh + n * PLD + k0);
                    vh[1] = *(const uint32_t*)(sKh + n * PLD + k0 + 8);
                    vl[0] = *(const uint32_t*)(sKl + n * PLD + k0);
                    vl[1] = *(const uint32_t*)(sKl + n * PLD + k0 + 8);
                    MMA16816(oacc[mi][ni], ph, vh);
                    MMA16816(oacc[mi][ni], ph, vl);
                    MMA16816(oacc[mi][ni], pl, vh);
                }
            }
        }
    }

    // ---- epilogue: normalize, split, store bf16 hi/lo ----
    #pragma unroll
    for (int mi = 0; mi < 2; mi++)
        #pragma unroll
        for (int hf = 0; hf < 2; hf++) {
            const int row = wr * 32 + mi * 16 + lr + 8 * hf;
            const size_t rowg = (size_t)(b * SS + qt * 128 + row);
            const float inv = 1.f / l[mi][hf];
            #pragma unroll
            for (int ni = 0; ni < 8; ni++) {
                const int col = head * 128 + wc * 64 + ni * 8 + (lq << 1);
                const float o0 = oacc[mi][ni][2*hf]   * inv;
                const float o1 = oacc[mi][ni][2*hf+1] * inv;
                const bf16 h0 = __float2bfloat16(o0);
                const bf16 h1 = __float2bfloat16(o1);
                *(__nv_bfloat162*)(Oh + rowg * HIDC + col) = __halves2bfloat162(h0, h1);
                *(__nv_bfloat162*)(Ol + rowg * HIDC + col) = __halves2bfloat162(
                    __float2bfloat16(o0 - __bfloat162float(h0)),
                    __float2bfloat16(o1 - __bfloat162float(h1)));
            }
        }
}

// ---------------------------------------------------------------------------
// Launch
// ---------------------------------------------------------------------------
extern "C" void kernel_launch(void* const* d_in, const int* in_sizes, int n_in,
                              void* d_out, int out_size)
{
    (void)in_sizes; (void)n_in; (void)out_size;
    const float* hidden = (const float*)d_in[0];
    const float* cosp   = (const float*)d_in[1];
    const float* sinp   = (const float*)d_in[2];
    const float* Wq     = (const float*)d_in[3];
    const float* bq     = (const float*)d_in[4];
    const float* Wk     = (const float*)d_in[5];
    const float* bk     = (const float*)d_in[6];
    const float* Wv     = (const float*)d_in[7];
    const float* bv     = (const float*)d_in[8];
    const float* Wo     = (const float*)d_in[9];
    float* out = (float*)d_out;

    bf16 *ah, *al, *wqh, *wql, *wkh, *wkl, *wvh, *wvl, *woh, *wol, *oth, *otl;
    float *q, *kv;
    cudaGetSymbolAddress((void**)&ah,  g_ah);
    cudaGetSymbolAddress((void**)&al,  g_al);
    cudaGetSymbolAddress((void**)&wqh, g_wqh);
    cudaGetSymbolAddress((void**)&wql, g_wql);
    cudaGetSymbolAddress((void**)&wkh, g_wkh);
    cudaGetSymbolAddress((void**)&wkl, g_wkl);
    cudaGetSymbolAddress((void**)&wvh, g_wvh);
    cudaGetSymbolAddress((void**)&wvl, g_wvl);
    cudaGetSymbolAddress((void**)&woh, g_woh);
    cudaGetSymbolAddress((void**)&wol, g_wol);
    cudaGetSymbolAddress((void**)&oth, g_oth);
    cudaGetSymbolAddress((void**)&otl, g_otl);
    cudaGetSymbolAddress((void**)&q,   g_q);
    cudaGetSymbolAddress((void**)&kv,  g_kv);

    cudaFuncSetAttribute(gemm_mma,
                         cudaFuncAttributeMaxDynamicSharedMemorySize, GSMEM);
    cudaFuncSetAttribute(attn_mma,
                         cudaFuncAttributeMaxDynamicSharedMemorySize, ATTN_SMEM);

    const dim3 tb(32, 8);
    // pre-passes: activation split + weight split-transpose
    {
        const int n4 = MROWS * HIDC / 4;
        split_kernel<<<(n4 + 255) / 256, 256>>>(hidden, ah, al, n4);
    }
    wsplitT_kernel<<<dim3(HIDC / 32, GK / 32), tb>>>(Wq, wqh, wql, HIDC);
    wsplitT_kernel<<<dim3((NKVC * HDC) / 32, GK / 32), tb>>>(Wk, wkh, wkl, NKVC * HDC);
    wsplitT_kernel<<<dim3((NKVC * HDC) / 32, GK / 32), tb>>>(Wv, wvh, wvl, NKVC * HDC);
    wsplitT_kernel<<<dim3(HIDC / 32, GK / 32), tb>>>(Wo, woh, wol, HIDC);

    // projections (tensor path)
    gemm_mma<<<dim3(HIDC / 128, MROWS / 128), 256, GSMEM>>>(ah, al, wqh, wql, bq, q, HIDC);
    gemm_mma<<<dim3((NKVC * HDC) / 128, MROWS / 128), 256, GSMEM>>>(ah, al, wkh, wkl, bk, kv, KVW);
    gemm_mma<<<dim3((NKVC * HDC) / 128, MROWS / 128), 256, GSMEM>>>(ah, al, wvh, wvl, bv, kv + NKVC * HDC, KVW);

    // RoPE on q and k-part of kv
    const int tq = MROWS * NHC * 16;
    rope_kernel<<<(tq + 255) / 256, 256>>>(q, cosp, sinp, NHC, NHC * HDC, tq);
    const int tk = MROWS * NKVC * 16;
    rope_kernel<<<(tk + 255) / 256, 256>>>(kv, cosp, sinp, NKVC, KVW, tk);

    // attention (tensor path, writes split bf16 output)
    attn_mma<<<dim3(SS / 128, NHC, BB), 256, ATTN_SMEM>>>(q, kv, oth, otl);

    // output projection
    gemm_mma<<<dim3(HIDC / 128, MROWS / 128), 256, GSMEM>>>(oth, otl, woh, wol, nullptr, out, HIDC);
}

// round 11
// speedup vs baseline: 3.5666x; 1.1406x over previous
#include <cuda_runtime.h>
#include <cuda_bf16.h>
#include <stdint.h>
#include <math.h>

// Problem constants
#define BB      2
#define SS      2048
#define HIDC    4096
#define NHC     32
#define NKVC    8
#define HDC     128
#define MROWS   (BB*SS)          // 4096
#define KVW     (2*NKVC*HDC)     // 2048 combined K|V row width
#define GK      4096             // reduction dim for every projection

typedef __nv_bfloat16 bf16;

// ---------------------------------------------------------------------------
// Tiled + swizzled global layout for all GEMM operands:
//   8KB tiles of 128 rows x 32 bf16. tile id = (row>>7)*128 + (k>>5)
//   (128 = GK/32 tiles along k). Within-tile byte offset carries an XOR
//   bank swizzle so a LINEAR bulk copy into smem is ldmatrix/LDS
//   conflict-free.
// ---------------------------------------------------------------------------
__device__ __forceinline__ uint32_t tile_off(uint32_t r, uint32_t k) {
    const uint32_t line = r >> 1;
    const uint32_t slot = (((r & 1u) << 2) | (k >> 3)) ^ (line & 7u);
    return line * 128u + slot * 16u + ((k & 7u) << 1);
}

// ---------------------------------------------------------------------------
// Scratch (device globals: the sanctioned alloc-free scratch path)
// ---------------------------------------------------------------------------
__device__ bf16  g_ah [(size_t)MROWS * HIDC];   // hidden hi  (tiled)
__device__ bf16  g_al [(size_t)MROWS * HIDC];   // hidden lo  (tiled)
__device__ bf16  g_wqh[(size_t)HIDC * GK];      // Wq^T hi [N][K] (tiled)
__device__ bf16  g_wql[(size_t)HIDC * GK];
__device__ bf16  g_wkh[(size_t)(NKVC*HDC) * GK];
__device__ bf16  g_wkl[(size_t)(NKVC*HDC) * GK];
__device__ bf16  g_wvh[(size_t)(NKVC*HDC) * GK];
__device__ bf16  g_wvl[(size_t)(NKVC*HDC) * GK];
__device__ bf16  g_woh[(size_t)HIDC * GK];
__device__ bf16  g_wol[(size_t)HIDC * GK];
__device__ bf16  g_oth[(size_t)MROWS * HIDC];   // att hi (tiled, from attn)
__device__ bf16  g_otl[(size_t)MROWS * HIDC];   // att lo (tiled)
__device__ float g_q  [(size_t)MROWS * HIDC];
__device__ float g_kv [(size_t)MROWS * KVW];    // [row][K(1024)|V(1024)]

// ---------------------------------------------------------------------------
// small helpers
// ---------------------------------------------------------------------------
__device__ __forceinline__ uint64_t gmem_u64(const void* p) {
    uint64_t a;
    asm("cvta.to.global.u64 %0, %1;" : "=l"(a) : "l"(p));
    return a;
}
__device__ __forceinline__ uint32_t smem_u32(const void* p) {
    uint32_t a;
    asm("{ .reg .u64 t; cvta.to.shared.u64 t, %1; cvt.u32.u64 %0, t; }" : "=r"(a) : "l"(p));
    return a;
}

#define MBAR_INIT(addr, cnt) \
    asm volatile("mbarrier.init.shared.b64 [%0], %1;" :: "r"((uint32_t)(addr)), "r"((uint32_t)(cnt)) : "memory")
#define MBAR_EXPECT_TX(addr, tx) \
    asm volatile("mbarrier.arrive.expect_tx.shared.b64 _, [%0], %1;" :: "r"((uint32_t)(addr)), "r"((uint32_t)(tx)) : "memory")
#define BULK_G2S(dst, src, bytes, mbar) \
    asm volatile("cp.async.bulk.shared::cluster.global.mbarrier::complete_tx::bytes [%0], [%1], %2, [%3];" \
        :: "r"((uint32_t)(dst)), "l"((uint64_t)(src)), "r"((uint32_t)(bytes)), "r"((uint32_t)(mbar)) : "memory")

#define MBAR_WAIT(mbar_addr, parity) do {                                         \
    uint32_t _m = (uint32_t)(mbar_addr); uint32_t _p = (uint32_t)(parity);        \
    uint32_t _done;                                                               \
    asm volatile("{\n\t.reg .pred p;\n\t"                                         \
        "mbarrier.try_wait.parity.acquire.cta.shared::cta.b64 p, [%1], %2;\n\t"   \
        "selp.b32 %0, 1, 0, p;\n\t}"                                              \
        : "=r"(_done) : "r"(_m), "r"(_p) : "memory");                             \
    if (!_done) {                                                                 \
        asm volatile("{\n\t.reg .pred P1;\n\t"                                    \
        "WL_%=:\n\t"                                                              \
        "mbarrier.try_wait.parity.acquire.cta.shared::cta.b64 P1, [%0], %1, 0x989680;\n\t" \
        "@P1 bra.uni WD_%=;\n\t"                                                  \
        "bra.uni WL_%=;\n\t"                                                      \
        "WD_%=:\n\t}" :: "r"(_m), "r"(_p) : "memory");                            \
    }                                                                             \
} while (0)

#define MMA16816(d, a, b) \
    asm volatile("mma.sync.aligned.m16n8k16.row.col.f32.bf16.bf16.f32 " \
        "{%0,%1,%2,%3}, {%4,%5,%6,%7}, {%8,%9}, {%0,%1,%2,%3};" \
        : "+f"((d)[0]), "+f"((d)[1]), "+f"((d)[2]), "+f"((d)[3]) \
        : "r"((a)[0]), "r"((a)[1]), "r"((a)[2]), "r"((a)[3]), \
          "r"((b)[0]), "r"((b)[1]))

// ---------------------------------------------------------------------------
// Pre-pass: hidden fp32 [M][GK] -> (hi, lo) bf16 TILED layout.
// One thread per 8-element group (coalesced read, one 16B store per split).
// ---------------------------------------------------------------------------
__global__ void split_kernel(const float* __restrict__ x, bf16* __restrict__ h,
                             bf16* __restrict__ l, int total8)
{
    int i = blockIdx.x * blockDim.x + threadIdx.x;
    if (i >= total8) return;
    const int row = i >> 9;                 // GK/8 = 512 groups per row
    const int k8  = (i & 511) << 3;
    const float4 v0 = *((const float4*)(x + (size_t)row * GK + k8));
    const float4 v1 = *((const float4*)(x + (size_t)row * GK + k8 + 4));
    const float vv[8] = {v0.x, v0.y, v0.z, v0.w, v1.x, v1.y, v1.z, v1.w};
    uint32_t hw[4], lw[4];
    #pragma unroll
    for (int j = 0; j < 4; j++) {
        const bf16 ha = __float2bfloat16(vv[2*j]);
        const bf16 hb = __float2bfloat16(vv[2*j+1]);
        __nv_bfloat162 hp = __halves2bfloat162(ha, hb);
        __nv_bfloat162 lp = __halves2bfloat162(
            __float2bfloat16(vv[2*j]   - __bfloat162float(ha)),
            __float2bfloat16(vv[2*j+1] - __bfloat162float(hb)));
        hw[j] = *(uint32_t*)&hp;
        lw[j] = *(uint32_t*)&lp;
    }
    const size_t   tb  = (((size_t)(row >> 7)) * 128 + (k8 >> 5)) * 8192;
    const uint32_t off = tile_off(row & 127, k8 & 31);
    *(uint4*)((char*)h + tb + off) = make_uint4(hw[0], hw[1], hw[2], hw[3]);
    *(uint4*)((char*)l + tb + off) = make_uint4(lw[0], lw[1], lw[2], lw[3]);
}

// ---------------------------------------------------------------------------
// Pre-pass: W[k][n] fp32 -> Wt_hi/Wt_lo [n][k] bf16 TILED layout.
// ---------------------------------------------------------------------------
__global__ void wsplitT_kernel(const float* __restrict__ W, bf16* __restrict__ th,
                               bf16* __restrict__ tl, int Ncols)
{
    __shared__ float t[32][33];
    const int bx = blockIdx.x * 32, by = blockIdx.y * 32;
    const int tx = threadIdx.x, ty = threadIdx.y;
    #pragma unroll
    for (int i = 0; i < 4; i++)
        t[ty + i * 8][tx] = W[(size_t)(by + ty + i * 8) * Ncols + bx + tx];
    __syncthreads();
    #pragma unroll
    for (int i = 0; i < 4; i++) {
        const float v = t[tx][ty + i * 8];
        const int n = bx + ty + i * 8;
        const int k = by + tx;
        const size_t   tb  = (((size_t)(n >> 7)) * 128 + (k >> 5)) * 8192;
        const uint32_t off = tile_off(n & 127, k & 31);
        const bf16 hh = __float2bfloat16(v);
        *(bf16*)((char*)th + tb + off) = hh;
        *(bf16*)((char*)tl + tb + off) = __float2bfloat16(v - __bfloat162float(hh));
    }
}

// ---------------------------------------------------------------------------
// 3x bf16-split GEMM via mma.sync, fed by cp.async.bulk (one thread issues
// 4 x 8KB bulk copies per chunk; the old 2048 per-thread cp.asyncs were the
// measured bottleneck at rt=8cyc/LDGSTS).
// CTA tile 128x128, BK=32, 8 warps (2x4) of 64x32, 3-stage mbarrier pipeline,
// 2 CTAs/SM. CTA swizzle (16-wide col groups) for L2 residency.
// ---------------------------------------------------------------------------
#define SPLB   8192                   // bytes per matrix per split per chunk
#define STAGEB (4*SPLB)               // 32768
#define NSTG   3
#define GSMEM  (NSTG*STAGEB + 64)     // + mbarriers

__global__ void __launch_bounds__(256, 2)
gemm_mma(const bf16* __restrict__ Ah, const bf16* __restrict__ Al,
         const bf16* __restrict__ Bh, const bf16* __restrict__ Bl,
         const float* __restrict__ bias, float* __restrict__ C, int ldC)
{
    extern __shared__ char smc[];
    const uint32_t smb  = smem_u32(smc);
    const uint32_t mbb  = smb + NSTG * STAGEB;       // 3 mbarriers @ +0,+8,+16
    const int tid  = threadIdx.x;
    const int lane = tid & 31, wid = tid >> 5;
    const int wr   = wid >> 2, wc = wid & 3;

    // CTA swizzle: 16-wide column groups
    int bx, by;
    {
        const int ntx = gridDim.x, nty = gridDim.y;
        const int id  = blockIdx.y * ntx + blockIdx.x;
        const int G   = (ntx < 16) ? ntx : 16;
        const int perg = G * nty;
        const int gg = id / perg, rr = id % perg;
        bx = gg * G + (rr % G);
        by = rr / G;
    }
    const int row0 = by << 7, col0 = bx << 7;

    const uint64_t gAh = gmem_u64(Ah), gAl = gmem_u64(Al);
    const uint64_t gBh = gmem_u64(Bh), gBl = gmem_u64(Bl);
    const uint64_t tA = ((uint64_t)(row0 >> 7)) * 128 * 8192;
    const uint64_t tB = ((uint64_t)(col0 >> 7)) * 128 * 8192;

    if (tid == 0) {
        MBAR_INIT(mbb + 0,  1);
        MBAR_INIT(mbb + 8,  1);
        MBAR_INIT(mbb + 16, 1);
    }
    __syncthreads();

    if (tid == 0) {
        #pragma unroll
        for (int c = 0; c < NSTG; c++) {
            const uint32_t mb = mbb + c * 8;
            const uint32_t dst = smb + c * STAGEB;
            const uint64_t ko = (uint64_t)c * 8192;
            MBAR_EXPECT_TX(mb, STAGEB);
            BULK_G2S(dst,            gAh + tA + ko, SPLB, mb);
            BULK_G2S(dst +   SPLB,   gAl + tA + ko, SPLB, mb);
            BULK_G2S(dst + 2*SPLB,   gBh + tB + ko, SPLB, mb);
            BULK_G2S(dst + 3*SPLB,   gBl + tB + ko, SPLB, mb);
        }
    }

    float acc[16][4];
    #pragma unroll
    for (int i = 0; i < 16; i++)
        #pragma unroll
        for (int j = 0; j < 4; j++) acc[i][j] = 0.f;

    const int lr = lane >> 2;            // 0..7
    const int lq = lane & 3;             // 0..3
    const int lk = lq << 1;

    #pragma unroll 1
    for (int c = 0; c < 128; c++) {
        const int s = c % NSTG;
        MBAR_WAIT(mbb + s * 8, (c / NSTG) & 1);

        const char* sb  = smc + s * STAGEB;
        const char* sAh = sb;
        const char* sAl = sb + SPLB;
        const char* sBh = sb + 2 * SPLB;
        const char* sBl = sb + 3 * SPLB;

        #pragma unroll
        for (int ks = 0; ks < 2; ks++) {
            const int kb = (ks << 4) + lk;
            uint32_t bhf[4][2], blf[4][2];
            #pragma unroll
            for (int ni = 0; ni < 4; ni++) {
                const int n = wc * 32 + ni * 8 + lr;
                bhf[ni][0] = *(const uint32_t*)(sBh + tile_off(n, kb));
                bhf[ni][1] = *(const uint32_t*)(sBh + tile_off(n, kb + 8));
                blf[ni][0] = *(const uint32_t*)(sBl + tile_off(n, kb));
                blf[ni][1] = *(const uint32_t*)(sBl + tile_off(n, kb + 8));
            }
            #pragma unroll
            for (int mi = 0; mi < 4; mi++) {
                const int r = wr * 64 + mi * 16 + lr;
                uint32_t ahf[4], alf[4];
                ahf[0] = *(const uint32_t*)(sAh + tile_off(r,     kb));
                ahf[1] = *(const uint32_t*)(sAh + tile_off(r + 8, kb));
                ahf[2] = *(const uint32_t*)(sAh + tile_off(r,     kb + 8));
                ahf[3] = *(const uint32_t*)(sAh + tile_off(r + 8, kb + 8));
                alf[0] = *(const uint32_t*)(sAl + tile_off(r,     kb));
                alf[1] = *(const uint32_t*)(sAl + tile_off(r + 8, kb));
                alf[2] = *(const uint32_t*)(sAl + tile_off(r,     kb + 8));
                alf[3] = *(const uint32_t*)(sAl + tile_off(r + 8, kb + 8));
                #pragma unroll
                for (int ni = 0; ni < 4; ni++) {
                    MMA16816(acc[mi * 4 + ni], ahf, bhf[ni]);
                    MMA16816(acc[mi * 4 + ni], ahf, blf[ni]);
                    MMA16816(acc[mi * 4 + ni], alf, bhf[ni]);
                }
            }
        }
        __syncthreads();                      // all threads done reading stage s
        if (tid == 0 && c + NSTG < 128) {
            const uint32_t mb = mbb + s * 8;
            const uint32_t dst = smb + s * STAGEB;
            const uint64_t ko = (uint64_t)(c + NSTG) * 8192;
            MBAR_EXPECT_TX(mb, STAGEB);
            BULK_G2S(dst,            gAh + tA + ko, SPLB, mb);
            BULK_G2S(dst +   SPLB,   gAl + tA + ko, SPLB, mb);
            BULK_G2S(dst + 2*SPLB,   gBh + tB + ko, SPLB, mb);
            BULK_G2S(dst + 3*SPLB,   gBl + tB + ko, SPLB, mb);
        }
    }

    // epilogue
    #pragma unroll
    for (int mi = 0; mi < 4; mi++) {
        const int r = row0 + wr * 64 + mi * 16 + lr;
        #pragma unroll
        for (int ni = 0; ni < 4; ni++) {
            const int cc = col0 + wc * 32 + ni * 8 + lk;
            float b0 = 0.f, b1 = 0.f;
            if (bias) { b0 = __ldg(bias + cc); b1 = __ldg(bias + cc + 1); }
            float* p0 = C + (size_t)r * ldC + cc;
            float* p1 = C + (size_t)(r + 8) * ldC + cc;
            p0[0] = acc[mi * 4 + ni][0] + b0;
            p0[1] = acc[mi * 4 + ni][1] + b1;
            p1[0] = acc[mi * 4 + ni][2] + b0;
            p1[1] = acc[mi * 4 + ni][3] + b1;
        }
    }
}

// ---------------------------------------------------------------------------
// RoPE (in place, float4)
// ---------------------------------------------------------------------------
__global__ void rope_kernel(float* __restrict__ x, const float* __restrict__ cs,
                            const float* __restrict__ sn, int nheads, int rowstride, int total)
{
    int p = blockIdx.x * blockDim.x + threadIdx.x;
    if (p >= total) return;
    const int d    = (p & 15) << 2;
    const int h    = (p >> 4) % nheads;
    const int sidx = p / (16 * nheads);
    float* base = x + (size_t)sidx * rowstride + h * HDC;
    const float* cb = cs + (size_t)sidx * HDC;
    const float* sb = sn + (size_t)sidx * HDC;
    const float4 x1 = *(const float4*)(base + d);
    const float4 x2 = *(const float4*)(base + d + 64);
    const float4 c1 = *(const float4*)(cb + d),      s1 = *(const float4*)(sb + d);
    const float4 c2 = *(const float4*)(cb + d + 64), s2 = *(const float4*)(sb + d + 64);
    float4 o1, o2;
    o1.x = x1.x * c1.x - x2.x * s1.x;  o1.y = x1.y * c1.y - x2.y * s1.y;
    o1.z = x1.z * c1.z - x2.z * s1.z;  o1.w = x1.w * c1.w - x2.w * s1.w;
    o2.x = x2.x * c2.x + x1.x * s2.x;  o2.y = x2.y * c2.y + x1.y * s2.y;
    o2.z = x2.z * c2.z + x1.z * s2.z;  o2.w = x2.w * c2.w + x1.w * s2.w;
    *(float4*)(base + d)      = o1;
    *(float4*)(base + d + 64) = o2;
}

// ---------------------------------------------------------------------------
// Flash attention on mma.sync bf16 with hi/lo split (3-term).
// Br=128 q-rows per CTA, Bc=64 keys per tile, 8 warps (4 row-groups x 2 col).
// Output written directly as (hi,lo) bf16 in the TILED layout for the O-GEMM.
// ---------------------------------------------------------------------------
#define ALD    136
#define PLD    72
#define OFF_QL (128*ALD*2)
#define OFF_KA (2*128*ALD*2)
#define OFF_KB (OFF_KA + 18432)
#define OFF_PH (OFF_KB + 18432)
#define OFF_PL (OFF_PH + 128*PLD*2)
#define OFF_MX (OFF_PL + 128*PLD*2)
#define OFF_SM (OFF_MX + 1024)
#define ATTN_SMEM (OFF_SM + 1024)
#define SCALE 0.08838834764831845f

__device__ __forceinline__ void split_st4(float4 v, bf16* dh, bf16* dl) {
    bf16 h0 = __float2bfloat16(v.x), h1 = __float2bfloat16(v.y);
    bf16 h2 = __float2bfloat16(v.z), h3 = __float2bfloat16(v.w);
    ((__nv_bfloat162*)dh)[0] = __halves2bfloat162(h0, h1);
    ((__nv_bfloat162*)dh)[1] = __halves2bfloat162(h2, h3);
    ((__nv_bfloat162*)dl)[0] = __halves2bfloat162(
        __float2bfloat16(v.x - __bfloat162float(h0)),
        __float2bfloat16(v.y - __bfloat162float(h1)));
    ((__nv_bfloat162*)dl)[1] = __halves2bfloat162(
        __float2bfloat16(v.z - __bfloat162float(h2)),
        __float2bfloat16(v.w - __bfloat162float(h3)));
}

__global__ void __launch_bounds__(256, 1)
attn_mma(const float* __restrict__ Q, const float* __restrict__ KV,
         bf16* __restrict__ Oh, bf16* __restrict__ Ol)
{
    extern __shared__ char sm[];
    bf16*  sQh = (bf16*)(sm);
    bf16*  sQl = (bf16*)(sm + OFF_QL);
    bf16*  sKh = (bf16*)(sm + OFF_KA);    // union: K hi | Vt hi
    bf16*  sKl = (bf16*)(sm + OFF_KB);    // union: K lo | Vt lo
    bf16*  sPh = (bf16*)(sm + OFF_PH);
    bf16*  sPl = (bf16*)(sm + OFF_PL);
    float* sMax = (float*)(sm + OFF_MX);
    float* sSum = (float*)(sm + OFF_SM);

    const int tid = threadIdx.x, lane = tid & 31, wid = tid >> 5;
    const int wr = wid >> 1, wc = wid & 1;
    const int lr = lane >> 2, lq = lane & 3;
    const int qt = blockIdx.x, head = blockIdx.y, b = blockIdx.z;
    const int kvh = head >> 2;

    {
        const float* qb = Q + ((size_t)(b * SS + qt * 128) * NHC + head) * HDC;
        #pragma unroll
        for (int i = 0; i < 16; i++) {
            const int id = tid + (i << 8);
            const int row = id >> 5, d0 = (id & 31) << 2;
            float4 v = *(const float4*)(qb + (size_t)row * (NHC * HDC) + d0);
            v.x *= SCALE; v.y *= SCALE; v.z *= SCALE; v.w *= SCALE;
            split_st4(v, sQh + row * ALD + d0, sQl + row * ALD + d0);
        }
    }

    float m[2][2], l[2][2];
    #pragma unroll
    for (int i = 0; i < 2; i++)
        #pragma unroll
        for (int j = 0; j < 2; j++) { m[i][j] = -INFINITY; l[i][j] = 0.f; }
    float oacc[2][8][4];
    #pragma unroll
    for (int a = 0; a < 2; a++)
        #pragma unroll
        for (int n = 0; n < 8; n++)
            #pragma unroll
            for (int r = 0; r < 4; r++) oacc[a][n][r] = 0.f;

    #pragma unroll 1
    for (int kt = 0; kt < SS / 64; kt++) {
        __syncthreads();

        {
            const float* kb = KV + (size_t)(b * SS + kt * 64) * KVW + kvh * HDC;
            #pragma unroll
            for (int i = 0; i < 8; i++) {
                const int id = tid + (i << 8);
                const int row = id >> 5, d0 = (id & 31) << 2;
                float4 v = *(const float4*)(kb + (size_t)row * KVW + d0);
                split_st4(v, sKh + row * ALD + d0, sKl + row * ALD + d0);
            }
        }
        __syncthreads();

        float sc[2][4][4];
        #pragma unroll
        for (int a = 0; a < 2; a++)
            #pragma unroll
            for (int n = 0; n < 4; n++)
                #pragma unroll
                for (int r = 0; r < 4; r++) sc[a][n][r] = 0.f;

        #pragma unroll
        for (int ks = 0; ks < 8; ks++) {
            const int k0 = (ks << 4) + (lq << 1);
            uint32_t bh[4][2], bl[4][2];
            #pragma unroll
            for (int ni = 0; ni < 4; ni++) {
                const int n = wc * 32 + ni * 8 + lr;
                bh[ni][0] = *(const uint32_t*)(sKh + n * ALD + k0);
                bh[ni][1] = *(const uint32_t*)(sKh + n * ALD + k0 + 8);
                bl[ni][0] = *(const uint32_t*)(sKl + n * ALD + k0);
                bl[ni][1] = *(const uint32_t*)(sKl + n * ALD + k0 + 8);
            }
            #pragma unroll
            for (int mi = 0; mi < 2; mi++) {
                const int r = wr * 32 + mi * 16 + lr;
                uint32_t ah[4], al[4];
                ah[0] = *(const uint32_t*)(sQh + r * ALD + k0);
                ah[1] = *(const uint32_t*)(sQh + (r + 8) * ALD + k0);
                ah[2] = *(const uint32_t*)(sQh + r * ALD + k0 + 8);
                ah[3] = *(const uint32_t*)(sQh + (r + 8) * ALD + k0 + 8);
                al[0] = *(const uint32_t*)(sQl + r * ALD + k0);
                al[1] = *(const uint32_t*)(sQl + (r + 8) * ALD + k0);
                al[2] = *(const uint32_t*)(sQl + r * ALD + k0 + 8);
                al[3] = *(const uint32_t*)(sQl + (r + 8) * ALD + k0 + 8);
                #pragma unroll
                for (int ni = 0; ni < 4; ni++) {
                    MMA16816(sc[mi][ni], ah, bh[ni]);
                    MMA16816(sc[mi][ni], ah, bl[ni]);
                    MMA16816(sc[mi][ni], al, bh[ni]);
                }
            }
        }

        #pragma unroll
        for (int mi = 0; mi < 2; mi++)
            #pragma unroll
            for (int hf = 0; hf < 2; hf++) {
                float mx = -INFINITY;
                #pragma unroll
                for (int ni = 0; ni < 4; ni++)
                    mx = fmaxf(mx, fmaxf(sc[mi][ni][2*hf], sc[mi][ni][2*hf+1]));
                mx = fmaxf(mx, __shfl_xor_sync(0xffffffffu, mx, 1));
                mx = fmaxf(mx, __shfl_xor_sync(0xffffffffu, mx, 2));
                if (lq == 0)
                    sMax[(wr * 32 + mi * 16 + lr + 8 * hf) * 2 + wc] = mx;
            }
        __syncthreads();

        float corr[2][2];
        #pragma unroll
        for (int mi = 0; mi < 2; mi++)
            #pragma unroll
            for (int hf = 0; hf < 2; hf++) {
                const int row = wr * 32 + mi * 16 + lr + 8 * hf;
                const float tmax = fmaxf(sMax[row * 2], sMax[row * 2 + 1]);
                const float mnew = fmaxf(m[mi][hf], tmax);
                corr[mi][hf] = __expf(m[mi][hf] - mnew);
                m[mi][hf] = mnew;
                float rs = 0.f;
                #pragma unroll
                for (int ni = 0; ni < 4; ni++) {
                    const float e0 = __expf(sc[mi][ni][2*hf]   - mnew);
                    const float e1 = __expf(sc[mi][ni][2*hf+1] - mnew);
                    rs += e0 + e1;
                    const bf16 h0 = __float2bfloat16(e0);
                    const bf16 h1 = __float2bfloat16(e1);
                    const int cc = wc * 32 + ni * 8 + (lq << 1);
                    *(__nv_bfloat162*)(sPh + row * PLD + cc) = __halves2bfloat162(h0, h1);
                    *(__nv_bfloat162*)(sPl + row * PLD + cc) = __halves2bfloat162(
                        __float2bfloat16(e0 - __bfloat162float(h0)),
                        __float2bfloat16(e1 - __bfloat162float(h1)));
                }
                rs += __shfl_xor_sync(0xffffffffu, rs, 1);
                rs += __shfl_xor_sync(0xffffffffu, rs, 2);
                if (lq == 0) sSum[row * 2 + wc] = rs;
                #pragma unroll
                for (int ni = 0; ni < 8; ni++) {
                    oacc[mi][ni][2*hf]   *= corr[mi][hf];
                    oacc[mi][ni][2*hf+1] *= corr[mi][hf];
                }
            }

        {
            const int kv0  = (tid & 31) * 2;
            const int dblk = (tid >> 5) * 16;
            const float* vb = KV + (size_t)(b * SS + kt * 64 + kv0) * KVW
                             + NKVC * HDC + kvh * HDC + dblk;
            #pragma unroll
            for (int j = 0; j < 4; j++) {
                const float4 v0 = *(const float4*)(vb + j * 4);
                const float4 v1 = *(const float4*)(vb + KVW + j * 4);
                const float e0[4] = {v0.x, v0.y, v0.z, v0.w};
                const float e1[4] = {v1.x, v1.y, v1.z, v1.w};
                #pragma unroll
                for (int e = 0; e < 4; e++) {
                    const int d = dblk + j * 4 + e;
                    const bf16 a0 = __float2bfloat16(e0[e]);
                    const bf16 a1 = __float2bfloat16(e1[e]);
                    *(__nv_bfloat162*)(sKh + d * PLD + kv0) = __halves2bfloat162(a0, a1);
                    *(__nv_bfloat162*)(sKl + d * PLD + kv0) = __halves2bfloat162(
                        __float2bfloat16(e0[e] - __bfloat162float(a0)),
                        __float2bfloat16(e1[e] - __bfloat162float(a1)));
                }
            }
        }
        __syncthreads();

        #pragma unroll
        for (int mi = 0; mi < 2; mi++)
            #pragma unroll
            for (int hf = 0; hf < 2; hf++) {
                const int row = wr * 32 + mi * 16 + lr + 8 * hf;
                l[mi][hf] = l[mi][hf] * corr[mi][hf] + sSum[row * 2] + sSum[row * 2 + 1];
            }

        #pragma unroll
        for (int ks = 0; ks < 4; ks++) {
            const int k0 = (ks << 4) + (lq << 1);
            #pragma unroll
            for (int mi = 0; mi < 2; mi++) {
                const int r = wr * 32 + mi * 16 + lr;
                uint32_t ph[4], pl[4];
                ph[0] = *(const uint32_t*)(sPh + r * PLD + k0);
                ph[1] = *(const uint32_t*)(sPh + (r + 8) * PLD + k0);
                ph[2] = *(const uint32_t*)(sPh + r * PLD + k0 + 8);
                ph[3] = *(const uint32_t*)(sPh + (r + 8) * PLD + k0 + 8);
                pl[0] = *(const uint32_t*)(sPl + r * PLD + k0);
                pl[1] = *(const uint32_t*)(sPl + (r + 8) * PLD + k0);
                pl[2] = *(const uint32_t*)(sPl + r * PLD + k0 + 8);
                pl[3] = *(const uint32_t*)(sPl + (r + 8) * PLD + k0 + 8);
                #pragma unroll
                for (int ni = 0; ni < 8; ni++) {
                    const int n = wc * 64 + ni * 8 + lr;
                    uint32_t vh[2], vl[2];
                    vh[0] = *(const uint32_t*)(sKh + n * PLD + k0);
                    vh[1] = *(const uint32_t*)(sKh + n * PLD + k0 + 8);
                    vl[0] = *(const uint32_t*)(sKl + n * PLD + k0);
                    vl[1] = *(const uint32_t*)(sKl + n * PLD + k0 + 8);
                    MMA16816(oacc[mi][ni], ph, vh);
                    MMA16816(oacc[mi][ni], ph, vl);
                    MMA16816(oacc[mi][ni], pl, vh);
                }
            }
        }
    }

    // ---- epilogue: normalize, split, store bf16 hi/lo in TILED layout ----
    #pragma unroll
    for (int mi = 0; mi < 2; mi++)
        #pragma unroll
        for (int hf = 0; hf < 2; hf++) {
            const int row = wr * 32 + mi * 16 + lr + 8 * hf;
            const size_t rowg = (size_t)(b * SS + qt * 128 + row);
            const float inv = 1.f / l[mi][hf];
            #pragma unroll
            for (int ni = 0; ni < 8; ni++) {
                const int colg = head * 128 + wc * 64 + ni * 8 + (lq << 1);
                const float o0 = oacc[mi][ni][2*hf]   * inv;
                const float o1 = oacc[mi][ni][2*hf+1] * inv;
                const bf16 h0 = __float2bfloat16(o0);
                const bf16 h1 = __float2bfloat16(o1);
                const size_t   tb  = ((rowg >> 7) * 128 + (size_t)(colg >> 5)) * 8192;
                const uint32_t off = tile_off((uint32_t)(rowg & 127), colg & 31);
                *(__nv_bfloat162*)((char*)Oh + tb + off) = __halves2bfloat162(h0, h1);
                *(__nv_bfloat162*)((char*)Ol + tb + off) = __halves2bfloat162(
                    __float2bfloat16(o0 - __bfloat162float(h0)),
                    __float2bfloat16(o1 - __bfloat162float(h1)));
            }
        }
}

// ---------------------------------------------------------------------------
// Launch
// ---------------------------------------------------------------------------
extern "C" void kernel_launch(void* const* d_in, const int* in_sizes, int n_in,
                              void* d_out, int out_size)
{
    (void)in_sizes; (void)n_in; (void)out_size;
    const float* hidden = (const float*)d_in[0];
    const float* cosp   = (const float*)d_in[1];
    const float* sinp   = (const float*)d_in[2];
    const float* Wq     = (const float*)d_in[3];
    const float* bq     = (const float*)d_in[4];
    const float* Wk     = (const float*)d_in[5];
    const float* bk     = (const float*)d_in[6];
    const float* Wv     = (const float*)d_in[7];
    const float* bv     = (const float*)d_in[8];
    const float* Wo     = (const float*)d_in[9];
    float* out = (float*)d_out;

    bf16 *ah, *al, *wqh, *wql, *wkh, *wkl, *wvh, *wvl, *woh, *wol, *oth, *otl;
    float *q, *kv;
    cudaGetSymbolAddress((void**)&ah,  g_ah);
    cudaGetSymbolAddress((void**)&al,  g_al);
    cudaGetSymbolAddress((void**)&wqh, g_wqh);
    cudaGetSymbolAddress((void**)&wql, g_wql);
    cudaGetSymbolAddress((void**)&wkh, g_wkh);
    cudaGetSymbolAddress((void**)&wkl, g_wkl);
    cudaGetSymbolAddress((void**)&wvh, g_wvh);
    cudaGetSymbolAddress((void**)&wvl, g_wvl);
    cudaGetSymbolAddress((void**)&woh, g_woh);
    cudaGetSymbolAddress((void**)&wol, g_wol);
    cudaGetSymbolAddress((void**)&oth, g_oth);
    cudaGetSymbolAddress((void**)&otl, g_otl);
    cudaGetSymbolAddress((void**)&q,   g_q);
    cudaGetSymbolAddress((void**)&kv,  g_kv);

    cudaFuncSetAttribute(gemm_mma,
                         cudaFuncAttributeMaxDynamicSharedMemorySize, GSMEM);
    cudaFuncSetAttribute(attn_mma,
                         cudaFuncAttributeMaxDynamicSharedMemorySize, ATTN_SMEM);

    const dim3 tb(32, 8);
    // pre-passes: activation split + weight split-transpose (tiled layout)
    {
        const int t8 = MROWS * HIDC / 8;
        split_kernel<<<(t8 + 255) / 256, 256>>>(hidden, ah, al, t8);
    }
    wsplitT_kernel<<<dim3(HIDC / 32, GK / 32), tb>>>(Wq, wqh, wql, HIDC);
    wsplitT_kernel<<<dim3((NKVC * HDC) / 32, GK / 32), tb>>>(Wk, wkh, wkl, NKVC * HDC);
    wsplitT_kernel<<<dim3((NKVC * HDC) / 32, GK / 32), tb>>>(Wv, wvh, wvl, NKVC * HDC);
    wsplitT_kernel<<<dim3(HIDC / 32, GK / 32), tb>>>(Wo, woh, wol, HIDC);

    // projections (tensor path, bulk-fed)
    gemm_mma<<<dim3(HIDC / 128, MROWS / 128), 256, GSMEM>>>(ah, al, wqh, wql, bq, q, HIDC);
    gemm_mma<<<dim3((NKVC * HDC) / 128, MROWS / 128), 256, GSMEM>>>(ah, al, wkh, wkl, bk, kv, KVW);
    gemm_mma<<<dim3((NKVC * HDC) / 128, MROWS / 128), 256, GSMEM>>>(ah, al, wvh, wvl, bv, kv + NKVC * HDC, KVW);

    // RoPE on q and k-part of kv
    const int tq = MROWS * NHC * 16;
    rope_kernel<<<(tq + 255) / 256, 256>>>(q, cosp, sinp, NHC, NHC * HDC, tq);
    const int tk = MROWS * NKVC * 16;
    rope_kernel<<<(tk + 255) / 256, 256>>>(kv, cosp, sinp, NKVC, KVW, tk);

    // attention (tensor path, writes tiled split bf16 output)
    attn_mma<<<dim3(SS / 128, NHC, BB), 256, ATTN_SMEM>>>(q, kv, oth, otl);

    // output projection
    gemm_mma<<<dim3(HIDC / 128, MROWS / 128), 256, GSMEM>>>(oth, otl, woh, wol, nullptr, out, HIDC);
}

// round 13
// speedup vs baseline: 3.8960x; 1.0924x over previous
#include <cuda_runtime.h>
#include <cuda_bf16.h>
#include <stdint.h>
#include <math.h>

// Problem constants
#define BB      2
#define SS      2048
#define HIDC    4096
#define NHC     32
#define NKVC    8
#define HDC     128
#define MROWS   (BB*SS)          // 4096
#define KVW     (2*NKVC*HDC)     // 2048 combined K|V row width
#define GK      4096             // reduction dim for every projection

typedef __nv_bfloat16 bf16;

// ---------------------------------------------------------------------------
// Tiled + swizzled global layout for all GEMM operands:
//   8KB tiles of 128 rows x 32 bf16. tile id = (row>>7)*128 + (k>>5).
//   Within-tile byte offset carries an XOR bank swizzle so a LINEAR bulk
//   copy into smem is ldmatrix/LDS conflict-free.
//   Affine properties used by the GEMM: +16 rows => +1024 bytes;
//   k halfstep (+16 k) => ^32; k group-of-8 => 16B-aligned slot.
// ---------------------------------------------------------------------------
__device__ __forceinline__ uint32_t tile_off(uint32_t r, uint32_t k) {
    const uint32_t line = r >> 1;
    const uint32_t slot = (((r & 1u) << 2) | (k >> 3)) ^ (line & 7u);
    return line * 128u + slot * 16u + ((k & 7u) << 1);
}

// ---------------------------------------------------------------------------
// Scratch (device globals: the sanctioned alloc-free scratch path)
// ---------------------------------------------------------------------------
__device__ bf16  g_ah [(size_t)MROWS * HIDC];   // hidden hi  (tiled)
__device__ bf16  g_al [(size_t)MROWS * HIDC];   // hidden lo  (tiled)
__device__ bf16  g_wqh[(size_t)HIDC * GK];      // Wq^T hi [N][K] (tiled)
__device__ bf16  g_wql[(size_t)HIDC * GK];
__device__ bf16  g_wkh[(size_t)(NKVC*HDC) * GK];
__device__ bf16  g_wkl[(size_t)(NKVC*HDC) * GK];
__device__ bf16  g_wvh[(size_t)(NKVC*HDC) * GK];
__device__ bf16  g_wvl[(size_t)(NKVC*HDC) * GK];
__device__ bf16  g_woh[(size_t)HIDC * GK];
__device__ bf16  g_wol[(size_t)HIDC * GK];
__device__ bf16  g_oth[(size_t)MROWS * HIDC];   // att hi (tiled, from attn)
__device__ bf16  g_otl[(size_t)MROWS * HIDC];   // att lo (tiled)
__device__ float g_q  [(size_t)MROWS * HIDC];
__device__ float g_kv [(size_t)MROWS * KVW];    // [row][K(1024)|V(1024)]

// ---------------------------------------------------------------------------
// small helpers
// ---------------------------------------------------------------------------
__device__ __forceinline__ uint64_t gmem_u64(const void* p) {
    uint64_t a;
    asm("cvta.to.global.u64 %0, %1;" : "=l"(a) : "l"(p));
    return a;
}
__device__ __forceinline__ uint32_t smem_u32(const void* p) {
    uint32_t a;
    asm("{ .reg .u64 t; cvta.to.shared.u64 t, %1; cvt.u32.u64 %0, t; }" : "=r"(a) : "l"(p));
    return a;
}

#define MBAR_INIT(addr, cnt) \
    asm volatile("mbarrier.init.shared.b64 [%0], %1;" :: "r"((uint32_t)(addr)), "r"((uint32_t)(cnt)) : "memory")
#define MBAR_EXPECT_TX(addr, tx) \
    asm volatile("mbarrier.arrive.expect_tx.shared.b64 _, [%0], %1;" :: "r"((uint32_t)(addr)), "r"((uint32_t)(tx)) : "memory")
#define BULK_G2S(dst, src, bytes, mbar) \
    asm volatile("cp.async.bulk.shared::cluster.global.mbarrier::complete_tx::bytes [%0], [%1], %2, [%3];" \
        :: "r"((uint32_t)(dst)), "l"((uint64_t)(src)), "r"((uint32_t)(bytes)), "r"((uint32_t)(mbar)) : "memory")

#define MBAR_WAIT(mbar_addr, parity) do {                                         \
    uint32_t _m = (uint32_t)(mbar_addr); uint32_t _p = (uint32_t)(parity);        \
    uint32_t _done;                                                               \
    asm volatile("{\n\t.reg .pred p;\n\t"                                         \
        "mbarrier.try_wait.parity.acquire.cta.shared::cta.b64 p, [%1], %2;\n\t"   \
        "selp.b32 %0, 1, 0, p;\n\t}"                                              \
        : "=r"(_done) : "r"(_m), "r"(_p) : "memory");                             \
    if (!_done) {                                                                 \
        asm volatile("{\n\t.reg .pred P1;\n\t"                                    \
        "WL_%=:\n\t"                                                              \
        "mbarrier.try_wait.parity.acquire.cta.shared::cta.b64 P1, [%0], %1, 0x989680;\n\t" \
        "@P1 bra.uni WD_%=;\n\t"                                                  \
        "bra.uni WL_%=;\n\t"                                                      \
        "WD_%=:\n\t}" :: "r"(_m), "r"(_p) : "memory");                            \
    }                                                                             \
} while (0)

#define MMA16816(d, a, b) \
    asm volatile("mma.sync.aligned.m16n8k16.row.col.f32.bf16.bf16.f32 " \
        "{%0,%1,%2,%3}, {%4,%5,%6,%7}, {%8,%9}, {%0,%1,%2,%3};" \
        : "+f"((d)[0]), "+f"((d)[1]), "+f"((d)[2]), "+f"((d)[3]) \
        : "r"((a)[0]), "r"((a)[1]), "r"((a)[2]), "r"((a)[3]), \
          "r"((b)[0]), "r"((b)[1]))

#define LDSM4(r0, r1, r2, r3, addr) \
    asm volatile("ldmatrix.sync.aligned.m8n8.x4.shared.b16 {%0,%1,%2,%3}, [%4];" \
        : "=r"(r0), "=r"(r1), "=r"(r2), "=r"(r3) : "r"((uint32_t)(addr)))

// ---------------------------------------------------------------------------
// Pre-pass: hidden fp32 [M][GK] -> (hi, lo) bf16 TILED layout.
// ---------------------------------------------------------------------------
__global__ void split_kernel(const float* __restrict__ x, bf16* __restrict__ h,
                             bf16* __restrict__ l, int total8)
{
    int i = blockIdx.x * blockDim.x + threadIdx.x;
    if (i >= total8) return;
    const int row = i >> 9;                 // GK/8 = 512 groups per row
    const int k8  = (i & 511) << 3;
    const float4 v0 = *((const float4*)(x + (size_t)row * GK + k8));
    const float4 v1 = *((const float4*)(x + (size_t)row * GK + k8 + 4));
    const float vv[8] = {v0.x, v0.y, v0.z, v0.w, v1.x, v1.y, v1.z, v1.w};
    uint32_t hw[4], lw[4];
    #pragma unroll
    for (int j = 0; j < 4; j++) {
        const bf16 ha = __float2bfloat16(vv[2*j]);
        const bf16 hb = __float2bfloat16(vv[2*j+1]);
        __nv_bfloat162 hp = __halves2bfloat162(ha, hb);
        __nv_bfloat162 lp = __halves2bfloat162(
            __float2bfloat16(vv[2*j]   - __bfloat162float(ha)),
            __float2bfloat16(vv[2*j+1] - __bfloat162float(hb)));
        hw[j] = *(uint32_t*)&hp;
        lw[j] = *(uint32_t*)&lp;
    }
    const size_t   tb  = (((size_t)(row >> 7)) * 128 + (k8 >> 5)) * 8192;
    const uint32_t off = tile_off(row & 127, k8 & 31);
    *(uint4*)((char*)h + tb + off) = make_uint4(hw[0], hw[1], hw[2], hw[3]);
    *(uint4*)((char*)l + tb + off) = make_uint4(lw[0], lw[1], lw[2], lw[3]);
}

// ---------------------------------------------------------------------------
// Pre-pass: W[k][n] fp32 -> Wt_hi/Wt_lo [n][k] bf16 TILED layout.
// ---------------------------------------------------------------------------
__global__ void wsplitT_kernel(const float* __restrict__ W, bf16* __restrict__ th,
                               bf16* __restrict__ tl, int Ncols)
{
    __shared__ float t[32][33];
    const int bx = blockIdx.x * 32, by = blockIdx.y * 32;
    const int tx = threadIdx.x, ty = threadIdx.y;
    #pragma unroll
    for (int i = 0; i < 4; i++)
        t[ty + i * 8][tx] = W[(size_t)(by + ty + i * 8) * Ncols + bx + tx];
    __syncthreads();
    #pragma unroll
    for (int i = 0; i < 4; i++) {
        const float v = t[tx][ty + i * 8];
        const int n = bx + ty + i * 8;
        const int k = by + tx;
        const size_t   tb  = (((size_t)(n >> 7)) * 128 + (k >> 5)) * 8192;
        const uint32_t off = tile_off(n & 127, k & 31);
        const bf16 hh = __float2bfloat16(v);
        *(bf16*)((char*)th + tb + off) = hh;
        *(bf16*)((char*)tl + tb + off) = __float2bfloat16(v - __bfloat162float(hh));
    }
}

// ---------------------------------------------------------------------------
// 3x bf16-split GEMM via mma.sync, bulk-copy fed, ldmatrix fragment loads.
// CTA tile 128x128, BK=32, 8 warps (2x4) of 64x32, 3-stage mbarrier pipeline,
// 2 CTAs/SM. Per warp per chunk: 24 LDSM.x4 + 96 HMMA (was 96 LDS + ~300 ALU).
// All LDSM addresses derived from 2 precomputed per-thread offsets via the
// tile layout's affine rules (+1024 per 16 rows, ^32 per k halfstep, +SPLB
// per split).
// ---------------------------------------------------------------------------
#define SPLB   8192                   // bytes per matrix per split per chunk
#define STAGEB (4*SPLB)               // 32768
#define NSTG   3
#define GSMEM  (NSTG*STAGEB + 64)     // + mbarriers

__global__ void __launch_bounds__(256, 2)
gemm_mma(const bf16* __restrict__ Ah, const bf16* __restrict__ Al,
         const bf16* __restrict__ Bh, const bf16* __restrict__ Bl,
         const float* __restrict__ bias, float* __restrict__ C, int ldC)
{
    extern __shared__ char smc[];
    const uint32_t smb  = smem_u32(smc);
    const uint32_t mbb  = smb + NSTG * STAGEB;       // 3 mbarriers @ +0,+8,+16
    const int tid  = threadIdx.x;
    const int lane = tid & 31, wid = tid >> 5;
    const int wr   = wid >> 2, wc = wid & 3;

    // CTA swizzle: 16-wide column groups for L2 residency
    int bx, by;
    {
        const int ntx = gridDim.x, nty = gridDim.y;
        const int id  = blockIdx.y * ntx + blockIdx.x;
        const int G   = (ntx < 16) ? ntx : 16;
        const int perg = G * nty;
        const int gg = id / perg, rr = id % perg;
        bx = gg * G + (rr % G);
        by = rr / G;
    }
    const int row0 = by << 7, col0 = bx << 7;

    const uint64_t gAh = gmem_u64(Ah), gAl = gmem_u64(Al);
    const uint64_t gBh = gmem_u64(Bh), gBl = gmem_u64(Bl);
    const uint64_t tA = ((uint64_t)(row0 >> 7)) * 128 * 8192;
    const uint64_t tB = ((uint64_t)(col0 >> 7)) * 128 * 8192;

    if (tid == 0) {
        MBAR_INIT(mbb + 0,  1);
        MBAR_INIT(mbb + 8,  1);
        MBAR_INIT(mbb + 16, 1);
    }
    __syncthreads();

    if (tid == 0) {
        #pragma unroll
        for (int c = 0; c < NSTG; c++) {
            const uint32_t mb = mbb + c * 8;
            const uint32_t dst = smb + c * STAGEB;
            const uint64_t ko = (uint64_t)c * 8192;
            MBAR_EXPECT_TX(mb, STAGEB);
            BULK_G2S(dst,            gAh + tA + ko, SPLB, mb);
            BULK_G2S(dst +   SPLB,   gAl + tA + ko, SPLB, mb);
            BULK_G2S(dst + 2*SPLB,   gBh + tB + ko, SPLB, mb);
            BULK_G2S(dst + 3*SPLB,   gBl + tB + ko, SPLB, mb);
        }
    }

    float acc[16][4];
    #pragma unroll
    for (int i = 0; i < 16; i++)
        #pragma unroll
        for (int j = 0; j < 4; j++) acc[i][j] = 0.f;

    // ldmatrix base offsets (per-thread, fixed modulo stage base):
    //  A x4 (16x16): lanes 0-15 -> rows 0-15 @k0, lanes 16-31 -> rows @k+8
    //  B x4 (pair of 8-col blocks): lanes 0-7 n0-7@k0, 8-15 n0-7@k8,
    //                               16-23 n8-15@k0, 24-31 n8-15@k8
    const uint32_t aoff = tile_off((uint32_t)(wr * 64 + (lane & 15)),
                                   (uint32_t)((lane >> 4) << 3));
    const uint32_t boff = 2 * SPLB +
        tile_off((uint32_t)(wc * 32 + ((lane >> 4) << 3) + (lane & 7)),
                 (uint32_t)(((lane >> 3) & 1) << 3));

    const int lq = lane & 3;
    const int lr = lane >> 2;
    const int lk = lq << 1;

    #pragma unroll 1
    for (int c = 0; c < 128; c++) {
        const int s = c % NSTG;
        MBAR_WAIT(mbb + s * 8, (c / NSTG) & 1);
        const uint32_t sb = smb + s * STAGEB;

        #pragma unroll
        for (int ks = 0; ks < 2; ks++) {
            const uint32_t kx = (uint32_t)(ks << 5);       // ^32 per k halfstep
            uint32_t bhf[4][2], blf[4][2];
            #pragma unroll
            for (int p = 0; p < 2; p++) {
                const uint32_t ba = sb + ((boff + p * 1024u) ^ kx);
                LDSM4(bhf[2*p][0], bhf[2*p][1], bhf[2*p+1][0], bhf[2*p+1][1], ba);
                LDSM4(blf[2*p][0], blf[2*p][1], blf[2*p+1][0], blf[2*p+1][1], ba + SPLB);
            }
            #pragma unroll
            for (int mi = 0; mi < 4; mi++) {
                const uint32_t aa = sb + ((aoff + mi * 1024u) ^ kx);
                uint32_t ahf[4], alf[4];
                LDSM4(ahf[0], ahf[1], ahf[2], ahf[3], aa);
                LDSM4(alf[0], alf[1], alf[2], alf[3], aa + SPLB);
                #pragma unroll
                for (int ni = 0; ni < 4; ni++) {
                    MMA16816(acc[mi * 4 + ni], ahf, bhf[ni]);
                    MMA16816(acc[mi * 4 + ni], ahf, blf[ni]);
                    MMA16816(acc[mi * 4 + ni], alf, bhf[ni]);
                }
            }
        }
        __syncthreads();                      // all threads done reading stage s
        if (tid == 0 && c + NSTG < 128) {
            const uint32_t mb = mbb + s * 8;
            const uint32_t dst = smb + s * STAGEB;
            const uint64_t ko = (uint64_t)(c + NSTG) * 8192;
            MBAR_EXPECT_TX(mb, STAGEB);
            BULK_G2S(dst,            gAh + tA + ko, SPLB, mb);
            BULK_G2S(dst +   SPLB,   gAl + tA + ko, SPLB, mb);
            BULK_G2S(dst + 2*SPLB,   gBh + tB + ko, SPLB, mb);
            BULK_G2S(dst + 3*SPLB,   gBl + tB + ko, SPLB, mb);
        }
    }

    // epilogue
    #pragma unroll
    for (int mi = 0; mi < 4; mi++) {
        const int r = row0 + wr * 64 + mi * 16 + lr;
        #pragma unroll
        for (int ni = 0; ni < 4; ni++) {
            const int cc = col0 + wc * 32 + ni * 8 + lk;
            float b0 = 0.f, b1 = 0.f;
            if (bias) { b0 = __ldg(bias + cc); b1 = __ldg(bias + cc + 1); }
            float* p0 = C + (size_t)r * ldC + cc;
            float* p1 = C + (size_t)(r + 8) * ldC + cc;
            p0[0] = acc[mi * 4 + ni][0] + b0;
            p0[1] = acc[mi * 4 + ni][1] + b1;
            p1[0] = acc[mi * 4 + ni][2] + b0;
            p1[1] = acc[mi * 4 + ni][3] + b1;
        }
    }
}

// ---------------------------------------------------------------------------
// RoPE (in place, float4)
// ---------------------------------------------------------------------------
__global__ void rope_kernel(float* __restrict__ x, const float* __restrict__ cs,
                            const float* __restrict__ sn, int nheads, int rowstride, int total)
{
    int p = blockIdx.x * blockDim.x + threadIdx.x;
    if (p >= total) return;
    const int d    = (p & 15) << 2;
    const int h    = (p >> 4) % nheads;
    const int sidx = p / (16 * nheads);
    float* base = x + (size_t)sidx * rowstride + h * HDC;
    const float* cb = cs + (size_t)sidx * HDC;
    const float* sb = sn + (size_t)sidx * HDC;
    const float4 x1 = *(const float4*)(base + d);
    const float4 x2 = *(const float4*)(base + d + 64);
    const float4 c1 = *(const float4*)(cb + d),      s1 = *(const float4*)(sb + d);
    const float4 c2 = *(const float4*)(cb + d + 64), s2 = *(const float4*)(sb + d + 64);
    float4 o1, o2;
    o1.x = x1.x * c1.x - x2.x * s1.x;  o1.y = x1.y * c1.y - x2.y * s1.y;
    o1.z = x1.z * c1.z - x2.z * s1.z;  o1.w = x1.w * c1.w - x2.w * s1.w;
    o2.x = x2.x * c2.x + x1.x * s2.x;  o2.y = x2.y * c2.y + x1.y * s2.y;
    o2.z = x2.z * c2.z + x1.z * s2.z;  o2.w = x2.w * c2.w + x1.w * s2.w;
    *(float4*)(base + d)      = o1;
    *(float4*)(base + d + 64) = o2;
}

// ---------------------------------------------------------------------------
// Flash attention on mma.sync bf16 with hi/lo split (3-term).
// Br=128 q-rows per CTA, Bc=64 keys per tile, 8 warps (4 row-groups x 2 col).
// Output written directly as (hi,lo) bf16 in the TILED layout for the O-GEMM.
// ---------------------------------------------------------------------------
#define ALD    136
#define PLD    72
#define OFF_QL (128*ALD*2)
#define OFF_KA (2*128*ALD*2)
#define OFF_KB (OFF_KA + 18432)
#define OFF_PH (OFF_KB + 18432)
#define OFF_PL (OFF_PH + 128*PLD*2)
#define OFF_MX (OFF_PL + 128*PLD*2)
#define OFF_SM (OFF_MX + 1024)
#define ATTN_SMEM (OFF_SM + 1024)
#define SCALE 0.08838834764831845f

__device__ __forceinline__ void split_st4(float4 v, bf16* dh, bf16* dl) {
    bf16 h0 = __float2bfloat16(v.x), h1 = __float2bfloat16(v.y);
    bf16 h2 = __float2bfloat16(v.z), h3 = __float2bfloat16(v.w);
    ((__nv_bfloat162*)dh)[0] = __halves2bfloat162(h0, h1);
    ((__nv_bfloat162*)dh)[1] = __halves2bfloat162(h2, h3);
    ((__nv_bfloat162*)dl)[0] = __halves2bfloat162(
        __float2bfloat16(v.x - __bfloat162float(h0)),
        __float2bfloat16(v.y - __bfloat162float(h1)));
    ((__nv_bfloat162*)dl)[1] = __halves2bfloat162(
        __float2bfloat16(v.z - __bfloat162float(h2)),
        __float2bfloat16(v.w - __bfloat162float(h3)));
}

__global__ void __launch_bounds__(256, 1)
attn_mma(const float* __restrict__ Q, const float* __restrict__ KV,
         bf16* __restrict__ Oh, bf16* __restrict__ Ol)
{
    extern __shared__ char sm[];
    bf16*  sQh = (bf16*)(sm);
    bf16*  sQl = (bf16*)(sm + OFF_QL);
    bf16*  sKh = (bf16*)(sm + OFF_KA);    // union: K hi | Vt hi
    bf16*  sKl = (bf16*)(sm + OFF_KB);    // union: K lo | Vt lo
    bf16*  sPh = (bf16*)(sm + OFF_PH);
    bf16*  sPl = (bf16*)(sm + OFF_PL);
    float* sMax = (float*)(sm + OFF_MX);
    float* sSum = (float*)(sm + OFF_SM);

    const int tid = threadIdx.x, lane = tid & 31, wid = tid >> 5;
    const int wr = wid >> 1, wc = wid & 1;
    const int lr = lane >> 2, lq = lane & 3;
    const int qt = blockIdx.x, head = blockIdx.y, b = blockIdx.z;
    const int kvh = head >> 2;

    {
        const float* qb = Q + ((size_t)(b * SS + qt * 128) * NHC + head) * HDC;
        #pragma unroll
        for (int i = 0; i < 16; i++) {
            const int id = tid + (i << 8);
            const int row = id >> 5, d0 = (id & 31) << 2;
            float4 v = *(const float4*)(qb + (size_t)row * (NHC * HDC) + d0);
            v.x *= SCALE; v.y *= SCALE; v.z *= SCALE; v.w *= SCALE;
            split_st4(v, sQh + row * ALD + d0, sQl + row * ALD + d0);
        }
    }

    float m[2][2], l[2][2];
    #pragma unroll
    for (int i = 0; i < 2; i++)
        #pragma unroll
        for (int j = 0; j < 2; j++) { m[i][j] = -INFINITY; l[i][j] = 0.f; }
    float oacc[2][8][4];
    #pragma unroll
    for (int a = 0; a < 2; a++)
        #pragma unroll
        for (int n = 0; n < 8; n++)
            #pragma unroll
            for (int r = 0; r < 4; r++) oacc[a][n][r] = 0.f;

    #pragma unroll 1
    for (int kt = 0; kt < SS / 64; kt++) {
        __syncthreads();

        {
            const float* kb = KV + (size_t)(b * SS + kt * 64) * KVW + kvh * HDC;
            #pragma unroll
            for (int i = 0; i < 8; i++) {
                const int id = tid + (i << 8);
                const int row = id >> 5, d0 = (id & 31) << 2;
                float4 v = *(const float4*)(kb + (size_t)row * KVW + d0);
                split_st4(v, sKh + row * ALD + d0, sKl + row * ALD + d0);
            }
        }
        __syncthreads();

        float sc[2][4][4];
        #pragma unroll
        for (int a = 0; a < 2; a++)
            #pragma unroll
            for (int n = 0; n < 4; n++)
                #pragma unroll
                for (int r = 0; r < 4; r++) sc[a][n][r] = 0.f;

        #pragma unroll
        for (int ks = 0; ks < 8; ks++) {
            const int k0 = (ks << 4) + (lq << 1);
            uint32_t bh[4][2], bl[4][2];
            #pragma unroll
            for (int ni = 0; ni < 4; ni++) {
                const int n = wc * 32 + ni * 8 + lr;
                bh[ni][0] = *(const uint32_t*)(sKh + n * ALD + k0);
                bh[ni][1] = *(const uint32_t*)(sKh + n * ALD + k0 + 8);
                bl[ni][0] = *(const uint32_t*)(sKl + n * ALD + k0);
                bl[ni][1] = *(const uint32_t*)(sKl + n * ALD + k0 + 8);
            }
            #pragma unroll
            for (int mi = 0; mi < 2; mi++) {
                const int r = wr * 32 + mi * 16 + lr;
                uint32_t ah[4], al[4];
                ah[0] = *(const uint32_t*)(sQh + r * ALD + k0);
                ah[1] = *(const uint32_t*)(sQh + (r + 8) * ALD + k0);
                ah[2] = *(const uint32_t*)(sQh + r * ALD + k0 + 8);
                ah[3] = *(const uint32_t*)(sQh + (r + 8) * ALD + k0 + 8);
                al[0] = *(const uint32_t*)(sQl + r * ALD + k0);
                al[1] = *(const uint32_t*)(sQl + (r + 8) * ALD + k0);
                al[2] = *(const uint32_t*)(sQl + r * ALD + k0 + 8);
                al[3] = *(const uint32_t*)(sQl + (r + 8) * ALD + k0 + 8);
                #pragma unroll
                for (int ni = 0; ni < 4; ni++) {
                    MMA16816(sc[mi][ni], ah, bh[ni]);
                    MMA16816(sc[mi][ni], ah, bl[ni]);
                    MMA16816(sc[mi][ni], al, bh[ni]);
                }
            }
        }

        #pragma unroll
        for (int mi = 0; mi < 2; mi++)
            #pragma unroll
            for (int hf = 0; hf < 2; hf++) {
                float mx = -INFINITY;
                #pragma unroll
                for (int ni = 0; ni < 4; ni++)
                    mx = fmaxf(mx, fmaxf(sc[mi][ni][2*hf], sc[mi][ni][2*hf+1]));
                mx = fmaxf(mx, __shfl_xor_sync(0xffffffffu, mx, 1));
                mx = fmaxf(mx, __shfl_xor_sync(0xffffffffu, mx, 2));
                if (lq == 0)
                    sMax[(wr * 32 + mi * 16 + lr + 8 * hf) * 2 + wc] = mx;
            }
        __syncthreads();

        float corr[2][2];
        #pragma unroll
        for (int mi = 0; mi < 2; mi++)
            #pragma unroll
            for (int hf = 0; hf < 2; hf++) {
                const int row = wr * 32 + mi * 16 + lr + 8 * hf;
                const float tmax = fmaxf(sMax[row * 2], sMax[row * 2 + 1]);
                const float mnew = fmaxf(m[mi][hf], tmax);
                corr[mi][hf] = __expf(m[mi][hf] - mnew);
                m[mi][hf] = mnew;
                float rs = 0.f;
                #pragma unroll
                for (int ni = 0; ni < 4; ni++) {
                    const float e0 = __expf(sc[mi][ni][2*hf]   - mnew);
                    const float e1 = __expf(sc[mi][ni][2*hf+1] - mnew);
                    rs += e0 + e1;
                    const bf16 h0 = __float2bfloat16(e0);
                    const bf16 h1 = __float2bfloat16(e1);
                    const int cc = wc * 32 + ni * 8 + (lq << 1);
                    *(__nv_bfloat162*)(sPh + row * PLD + cc) = __halves2bfloat162(h0, h1);
                    *(__nv_bfloat162*)(sPl + row * PLD + cc) = __halves2bfloat162(
                        __float2bfloat16(e0 - __bfloat162float(h0)),
                        __float2bfloat16(e1 - __bfloat162float(h1)));
                }
                rs += __shfl_xor_sync(0xffffffffu, rs, 1);
                rs += __shfl_xor_sync(0xffffffffu, rs, 2);
                if (lq == 0) sSum[row * 2 + wc] = rs;
                #pragma unroll
                for (int ni = 0; ni < 8; ni++) {
                    oacc[mi][ni][2*hf]   *= corr[mi][hf];
                    oacc[mi][ni][2*hf+1] *= corr[mi][hf];
                }
            }

        {
            const int kv0  = (tid & 31) * 2;
            const int dblk = (tid >> 5) * 16;
            const float* vb = KV + (size_t)(b * SS + kt * 64 + kv0) * KVW
                             + NKVC * HDC + kvh * HDC + dblk;
            #pragma unroll
            for (int j = 0; j < 4; j++) {
                const float4 v0 = *(const float4*)(vb + j * 4);
                const float4 v1 = *(const float4*)(vb + KVW + j * 4);
                const float e0[4] = {v0.x, v0.y, v0.z, v0.w};
                const float e1[4] = {v1.x, v1.y, v1.z, v1.w};
                #pragma unroll
                for (int e = 0; e < 4; e++) {
                    const int d = dblk + j * 4 + e;
                    const bf16 a0 = __float2bfloat16(e0[e]);
                    const bf16 a1 = __float2bfloat16(e1[e]);
                    *(__nv_bfloat162*)(sKh + d * PLD + kv0) = __halves2bfloat162(a0, a1);
                    *(__nv_bfloat162*)(sKl + d * PLD + kv0) = __halves2bfloat162(
                        __float2bfloat16(e0[e] - __bfloat162float(a0)),
                        __float2bfloat16(e1[e] - __bfloat162float(a1)));
                }
            }
        }
        __syncthreads();

        #pragma unroll
        for (int mi = 0; mi < 2; mi++)
            #pragma unroll
            for (int hf = 0; hf < 2; hf++) {
                const int row = wr * 32 + mi * 16 + lr + 8 * hf;
                l[mi][hf] = l[mi][hf] * corr[mi][hf] + sSum[row * 2] + sSum[row * 2 + 1];
            }

        #pragma unroll
        for (int ks = 0; ks < 4; ks++) {
            const int k0 = (ks << 4) + (lq << 1);
            #pragma unroll
            for (int mi = 0; mi < 2; mi++) {
                const int r = wr * 32 + mi * 16 + lr;
                uint32_t ph[4], pl[4];
                ph[0] = *(const uint32_t*)(sPh + r * PLD + k0);
                ph[1] = *(const uint32_t*)(sPh + (r + 8) * PLD + k0);
                ph[2] = *(const uint32_t*)(sPh + r * PLD + k0 + 8);
                ph[3] = *(const uint32_t*)(sPh + (r + 8) * PLD + k0 + 8);
                pl[0] = *(const uint32_t*)(sPl + r * PLD + k0);
                pl[1] = *(const uint32_t*)(sPl + (r + 8) * PLD + k0);
                pl[2] = *(const uint32_t*)(sPl + r * PLD + k0 + 8);
                pl[3] = *(const uint32_t*)(sPl + (r + 8) * PLD + k0 + 8);
                #pragma unroll
                for (int ni = 0; ni < 8; ni++) {
                    const int n = wc * 64 + ni * 8 + lr;
                    uint32_t vh[2], vl[2];
                    vh[0] = *(const uint32_t*)(sKh + n * PLD + k0);
                    vh[1] = *(const uint32_t*)(sKh + n * PLD + k0 + 8);
                    vl[0] = *(const uint32_t*)(sKl + n * PLD + k0);
                    vl[1] = *(const uint32_t*)(sKl + n * PLD + k0 + 8);
                    MMA16816(oacc[mi][ni], ph, vh);
                    MMA16816(oacc[mi][ni], ph, vl);
                    MMA16816(oacc[mi][ni], pl, vh);
                }
            }
        }
    }

    // ---- epilogue: normalize, split, store bf16 hi/lo in TILED layout ----
    #pragma unroll
    for (int mi = 0; mi < 2; mi++)
        #pragma unroll
        for (int hf = 0; hf < 2; hf++) {
            const int row = wr * 32 + mi * 16 + lr + 8 * hf;
            const size_t rowg = (size_t)(b * SS + qt * 128 + row);
            const float inv = 1.f / l[mi][hf];
            #pragma unroll
            for (int ni = 0; ni < 8; ni++) {
                const int colg = head * 128 + wc * 64 + ni * 8 + (lq << 1);
                const float o0 = oacc[mi][ni][2*hf]   * inv;
                const float o1 = oacc[mi][ni][2*hf+1] * inv;
                const bf16 h0 = __float2bfloat16(o0);
                const bf16 h1 = __float2bfloat16(o1);
                const size_t   tb  = ((rowg >> 7) * 128 + (size_t)(colg >> 5)) * 8192;
                const uint32_t off = tile_off((uint32_t)(rowg & 127), colg & 31);
                *(__nv_bfloat162*)((char*)Oh + tb + off) = __halves2bfloat162(h0, h1);
                *(__nv_bfloat162*)((char*)Ol + tb + off) = __halves2bfloat162(
                    __float2bfloat16(o0 - __bfloat162float(h0)),
                    __float2bfloat16(o1 - __bfloat162float(h1)));
            }
        }
}

// ---------------------------------------------------------------------------
// Launch
// ---------------------------------------------------------------------------
extern "C" void kernel_launch(void* const* d_in, const int* in_sizes, int n_in,
                              void* d_out, int out_size)
{
    (void)in_sizes; (void)n_in; (void)out_size;
    const float* hidden = (const float*)d_in[0];
    const float* cosp   = (const float*)d_in[1];
    const float* sinp   = (const float*)d_in[2];
    const float* Wq     = (const float*)d_in[3];
    const float* bq     = (const float*)d_in[4];
    const float* Wk     = (const float*)d_in[5];
    const float* bk     = (const float*)d_in[6];
    const float* Wv     = (const float*)d_in[7];
    const float* bv     = (const float*)d_in[8];
    const float* Wo     = (const float*)d_in[9];
    float* out = (float*)d_out;

    bf16 *ah, *al, *wqh, *wql, *wkh, *wkl, *wvh, *wvl, *woh, *wol, *oth, *otl;
    float *q, *kv;
    cudaGetSymbolAddress((void**)&ah,  g_ah);
    cudaGetSymbolAddress((void**)&al,  g_al);
    cudaGetSymbolAddress((void**)&wqh, g_wqh);
    cudaGetSymbolAddress((void**)&wql, g_wql);
    cudaGetSymbolAddress((void**)&wkh, g_wkh);
    cudaGetSymbolAddress((void**)&wkl, g_wkl);
    cudaGetSymbolAddress((void**)&wvh, g_wvh);
    cudaGetSymbolAddress((void**)&wvl, g_wvl);
    cudaGetSymbolAddress((void**)&woh, g_woh);
    cudaGetSymbolAddress((void**)&wol, g_wol);
    cudaGetSymbolAddress((void**)&oth, g_oth);
    cudaGetSymbolAddress((void**)&otl, g_otl);
    cudaGetSymbolAddress((void**)&q,   g_q);
    cudaGetSymbolAddress((void**)&kv,  g_kv);

    cudaFuncSetAttribute(gemm_mma,
                         cudaFuncAttributeMaxDynamicSharedMemorySize, GSMEM);
    cudaFuncSetAttribute(attn_mma,
                         cudaFuncAttributeMaxDynamicSharedMemorySize, ATTN_SMEM);

    const dim3 tb(32, 8);
    // pre-passes: activation split + weight split-transpose (tiled layout)
    {
        const int t8 = MROWS * HIDC / 8;
        split_kernel<<<(t8 + 255) / 256, 256>>>(hidden, ah, al, t8);
    }
    wsplitT_kernel<<<dim3(HIDC / 32, GK / 32), tb>>>(Wq, wqh, wql, HIDC);
    wsplitT_kernel<<<dim3((NKVC * HDC) / 32, GK / 32), tb>>>(Wk, wkh, wkl, NKVC * HDC);
    wsplitT_kernel<<<dim3((NKVC * HDC) / 32, GK / 32), tb>>>(Wv, wvh, wvl, NKVC * HDC);
    wsplitT_kernel<<<dim3(HIDC / 32, GK / 32), tb>>>(Wo, woh, wol, HIDC);

    // projections (tensor path, bulk-fed, ldmatrix loads)
    gemm_mma<<<dim3(HIDC / 128, MROWS / 128), 256, GSMEM>>>(ah, al, wqh, wql, bq, q, HIDC);
    gemm_mma<<<dim3((NKVC * HDC) / 128, MROWS / 128), 256, GSMEM>>>(ah, al, wkh, wkl, bk, kv, KVW);
    gemm_mma<<<dim3((NKVC * HDC) / 128, MROWS / 128), 256, GSMEM>>>(ah, al, wvh, wvl, bv, kv + NKVC * HDC, KVW);

    // RoPE on q and k-part of kv
    const int tq = MROWS * NHC * 16;
    rope_kernel<<<(tq + 255) / 256, 256>>>(q, cosp, sinp, NHC, NHC * HDC, tq);
    const int tk = MROWS * NKVC * 16;
    rope_kernel<<<(tk + 255) / 256, 256>>>(kv, cosp, sinp, NKVC, KVW, tk);

    // attention (tensor path, writes tiled split bf16 output)
    attn_mma<<<dim3(SS / 128, NHC, BB), 256, ATTN_SMEM>>>(q, kv, oth, otl);

    // output projection
    gemm_mma<<<dim3(HIDC / 128, MROWS / 128), 256, GSMEM>>>(oth, otl, woh, wol, nullptr, out, HIDC);
}

// round 14
// speedup vs baseline: 4.0119x; 1.0297x over previous
#include <cuda_runtime.h>
#include <cuda_bf16.h>
#include <stdint.h>
#include <math.h>

// Problem constants
#define BB      2
#define SS      2048
#define HIDC    4096
#define NHC     32
#define NKVC    8
#define HDC     128
#define MROWS   (BB*SS)          // 4096
#define KVW     (2*NKVC*HDC)     // 2048 combined K|V row width
#define GK      4096             // reduction dim for every projection

typedef __nv_bfloat16 bf16;

// ---------------------------------------------------------------------------
// Tiled + swizzled global layout for all GEMM operands:
//   8KB tiles of 128 rows x 32 bf16. tile id = (row>>7)*128 + (k>>5).
//   Within-tile byte offset carries an XOR bank swizzle so a LINEAR bulk
//   copy into smem is ldmatrix/LDS conflict-free.
//   Affine properties used by the GEMM: +16 rows => +1024 bytes;
//   k halfstep (+16 k) => ^32; k group-of-8 => 16B-aligned slot.
// ---------------------------------------------------------------------------
__device__ __forceinline__ uint32_t tile_off(uint32_t r, uint32_t k) {
    const uint32_t line = r >> 1;
    const uint32_t slot = (((r & 1u) << 2) | (k >> 3)) ^ (line & 7u);
    return line * 128u + slot * 16u + ((k & 7u) << 1);
}

// ---------------------------------------------------------------------------
// Scratch (device globals: the sanctioned alloc-free scratch path)
// ---------------------------------------------------------------------------
__device__ bf16  g_ah  [(size_t)MROWS * HIDC];   // hidden hi  (tiled)
__device__ bf16  g_al  [(size_t)MROWS * HIDC];   // hidden lo  (tiled)
__device__ bf16  g_wqh [(size_t)HIDC * GK];      // Wq^T hi [N][K] (tiled)
__device__ bf16  g_wql [(size_t)HIDC * GK];
__device__ bf16  g_wkvh[(size_t)KVW  * GK];      // [Wk^T | Wv^T] hi (tiled)
__device__ bf16  g_wkvl[(size_t)KVW  * GK];
__device__ bf16  g_woh [(size_t)HIDC * GK];
__device__ bf16  g_wol [(size_t)HIDC * GK];
__device__ bf16  g_oth [(size_t)MROWS * HIDC];   // att hi (tiled, from attn)
__device__ bf16  g_otl [(size_t)MROWS * HIDC];   // att lo (tiled)
__device__ float g_q   [(size_t)MROWS * HIDC];
__device__ float g_kv  [(size_t)MROWS * KVW];    // [row][K(1024)|V(1024)]
__device__ float g_bkv [KVW];

// ---------------------------------------------------------------------------
// small helpers
// ---------------------------------------------------------------------------
__device__ __forceinline__ uint64_t gmem_u64(const void* p) {
    uint64_t a;
    asm("cvta.to.global.u64 %0, %1;" : "=l"(a) : "l"(p));
    return a;
}
__device__ __forceinline__ uint32_t smem_u32(const void* p) {
    uint32_t a;
    asm("{ .reg .u64 t; cvta.to.shared.u64 t, %1; cvt.u32.u64 %0, t; }" : "=r"(a) : "l"(p));
    return a;
}

#define MBAR_INIT(addr, cnt) \
    asm volatile("mbarrier.init.shared.b64 [%0], %1;" :: "r"((uint32_t)(addr)), "r"((uint32_t)(cnt)) : "memory")
#define MBAR_EXPECT_TX(addr, tx) \
    asm volatile("mbarrier.arrive.expect_tx.shared.b64 _, [%0], %1;" :: "r"((uint32_t)(addr)), "r"((uint32_t)(tx)) : "memory")
#define MBAR_ARRIVE(addr) \
    asm volatile("mbarrier.arrive.shared.b64 _, [%0];" :: "r"((uint32_t)(addr)) : "memory")
#define BULK_G2S(dst, src, bytes, mbar) \
    asm volatile("cp.async.bulk.shared::cluster.global.mbarrier::complete_tx::bytes [%0], [%1], %2, [%3];" \
        :: "r"((uint32_t)(dst)), "l"((uint64_t)(src)), "r"((uint32_t)(bytes)), "r"((uint32_t)(mbar)) : "memory")

#define MBAR_WAIT(mbar_addr, parity) do {                                         \
    uint32_t _m = (uint32_t)(mbar_addr); uint32_t _p = (uint32_t)(parity);        \
    uint32_t _done;                                                               \
    asm volatile("{\n\t.reg .pred p;\n\t"                                         \
        "mbarrier.try_wait.parity.acquire.cta.shared::cta.b64 p, [%1], %2;\n\t"   \
        "selp.b32 %0, 1, 0, p;\n\t}"                                              \
        : "=r"(_done) : "r"(_m), "r"(_p) : "memory");                             \
    if (!_done) {                                                                 \
        asm volatile("{\n\t.reg .pred P1;\n\t"                                    \
        "WL_%=:\n\t"                                                              \
        "mbarrier.try_wait.parity.acquire.cta.shared::cta.b64 P1, [%0], %1, 0x989680;\n\t" \
        "@P1 bra.uni WD_%=;\n\t"                                                  \
        "bra.uni WL_%=;\n\t"                                                      \
        "WD_%=:\n\t}" :: "r"(_m), "r"(_p) : "memory");                            \
    }                                                                             \
} while (0)

#define MMA16816(d, a, b) \
    asm volatile("mma.sync.aligned.m16n8k16.row.col.f32.bf16.bf16.f32 " \
        "{%0,%1,%2,%3}, {%4,%5,%6,%7}, {%8,%9}, {%0,%1,%2,%3};" \
        : "+f"((d)[0]), "+f"((d)[1]), "+f"((d)[2]), "+f"((d)[3]) \
        : "r"((a)[0]), "r"((a)[1]), "r"((a)[2]), "r"((a)[3]), \
          "r"((b)[0]), "r"((b)[1]))

#define LDSM4(r0, r1, r2, r3, addr) \
    asm volatile("ldmatrix.sync.aligned.m8n8.x4.shared.b16 {%0,%1,%2,%3}, [%4];" \
        : "=r"(r0), "=r"(r1), "=r"(r2), "=r"(r3) : "r"((uint32_t)(addr)))

// ---------------------------------------------------------------------------
// Pre-pass: hidden fp32 [M][GK] -> (hi, lo) bf16 TILED layout.
// ---------------------------------------------------------------------------
__global__ void split_kernel(const float* __restrict__ x, bf16* __restrict__ h,
                             bf16* __restrict__ l, int total8)
{
    int i = blockIdx.x * blockDim.x + threadIdx.x;
    if (i >= total8) return;
    const int row = i >> 9;                 // GK/8 = 512 groups per row
    const int k8  = (i & 511) << 3;
    const float4 v0 = *((const float4*)(x + (size_t)row * GK + k8));
    const float4 v1 = *((const float4*)(x + (size_t)row * GK + k8 + 4));
    const float vv[8] = {v0.x, v0.y, v0.z, v0.w, v1.x, v1.y, v1.z, v1.w};
    uint32_t hw[4], lw[4];
    #pragma unroll
    for (int j = 0; j < 4; j++) {
        const bf16 ha = __float2bfloat16(vv[2*j]);
        const bf16 hb = __float2bfloat16(vv[2*j+1]);
        __nv_bfloat162 hp = __halves2bfloat162(ha, hb);
        __nv_bfloat162 lp = __halves2bfloat162(
            __float2bfloat16(vv[2*j]   - __bfloat162float(ha)),
            __float2bfloat16(vv[2*j+1] - __bfloat162float(hb)));
        hw[j] = *(uint32_t*)&hp;
        lw[j] = *(uint32_t*)&lp;
    }
    const size_t   tb  = (((size_t)(row >> 7)) * 128 + (k8 >> 5)) * 8192;
    const uint32_t off = tile_off(row & 127, k8 & 31);
    *(uint4*)((char*)h + tb + off) = make_uint4(hw[0], hw[1], hw[2], hw[3]);
    *(uint4*)((char*)l + tb + off) = make_uint4(lw[0], lw[1], lw[2], lw[3]);
}

// ---------------------------------------------------------------------------
// Pre-pass: W[k][n] fp32 -> Wt_hi/Wt_lo [n][k] bf16 TILED layout.
// ---------------------------------------------------------------------------
__global__ void wsplitT_kernel(const float* __restrict__ W, bf16* __restrict__ th,
                               bf16* __restrict__ tl, int Ncols)
{
    __shared__ float t[32][33];
    const int bx = blockIdx.x * 32, by = blockIdx.y * 32;
    const int tx = threadIdx.x, ty = threadIdx.y;
    #pragma unroll
    for (int i = 0; i < 4; i++)
        t[ty + i * 8][tx] = W[(size_t)(by + ty + i * 8) * Ncols + bx + tx];
    __syncthreads();
    #pragma unroll
    for (int i = 0; i < 4; i++) {
        const float v = t[tx][ty + i * 8];
        const int n = bx + ty + i * 8;
        const int k = by + tx;
        const size_t   tb  = (((size_t)(n >> 7)) * 128 + (k >> 5)) * 8192;
        const uint32_t off = tile_off(n & 127, k & 31);
        const bf16 hh = __float2bfloat16(v);
        *(bf16*)((char*)th + tb + off) = hh;
        *(bf16*)((char*)tl + tb + off) = __float2bfloat16(v - __bfloat162float(hh));
    }
}

__global__ void concat_bias(const float* __restrict__ bk, const float* __restrict__ bv,
                            float* __restrict__ bkv)
{
    int i = blockIdx.x * blockDim.x + threadIdx.x;
    if (i < NKVC * HDC)       bkv[i] = bk[i];
    else if (i < KVW)         bkv[i] = bv[i - NKVC * HDC];
}

// ---------------------------------------------------------------------------
// 3x bf16-split GEMM via mma.sync, bulk-copy fed, ldmatrix fragment loads.
// CTA tile 128x128, BK=32, 8 warps (2x4) of 64x32, 3-stage pipeline with
// full/empty mbarrier pairs (NO per-chunk __syncthreads: consumers arrive on
// the stage's empty barrier and run ahead; only tid0 blocks on it before
// reissuing the bulk copy). 2 CTAs/SM.
// ---------------------------------------------------------------------------
#define SPLB   8192                   // bytes per matrix per split per chunk
#define STAGEB (4*SPLB)               // 32768
#define NSTG   3
#define GSMEM  (NSTG*STAGEB + 64)     // + mbarriers (3 full @0/8/16, 3 empty @24/32/40)

__global__ void __launch_bounds__(256, 2)
gemm_mma(const bf16* __restrict__ Ah, const bf16* __restrict__ Al,
         const bf16* __restrict__ Bh, const bf16* __restrict__ Bl,
         const float* __restrict__ bias, float* __restrict__ C, int ldC)
{
    extern __shared__ char smc[];
    const uint32_t smb  = smem_u32(smc);
    const uint32_t mbf  = smb + NSTG * STAGEB;       // full mbarriers
    const uint32_t mbe  = mbf + 24;                  // empty mbarriers
    const int tid  = threadIdx.x;
    const int lane = tid & 31, wid = tid >> 5;
    const int wr   = wid >> 2, wc = wid & 3;

    // CTA swizzle: 16-wide column groups for L2 residency
    int bx, by;
    {
        const int ntx = gridDim.x, nty = gridDim.y;
        const int id  = blockIdx.y * ntx + blockIdx.x;
        const int G   = (ntx < 16) ? ntx : 16;
        const int perg = G * nty;
        const int gg = id / perg, rr = id % perg;
        bx = gg * G + (rr % G);
        by = rr / G;
    }
    const int row0 = by << 7, col0 = bx << 7;

    const uint64_t gAh = gmem_u64(Ah), gAl = gmem_u64(Al);
    const uint64_t gBh = gmem_u64(Bh), gBl = gmem_u64(Bl);
    const uint64_t tA = ((uint64_t)(row0 >> 7)) * 128 * 8192;
    const uint64_t tB = ((uint64_t)(col0 >> 7)) * 128 * 8192;

    if (tid == 0) {
        MBAR_INIT(mbf + 0,  1);
        MBAR_INIT(mbf + 8,  1);
        MBAR_INIT(mbf + 16, 1);
        MBAR_INIT(mbe + 0,  256);
        MBAR_INIT(mbe + 8,  256);
        MBAR_INIT(mbe + 16, 256);
    }
    __syncthreads();

    if (tid == 0) {
        #pragma unroll
        for (int c = 0; c < NSTG; c++) {
            const uint32_t mb = mbf + c * 8;
            const uint32_t dst = smb + c * STAGEB;
            const uint64_t ko = (uint64_t)c * 8192;
            MBAR_EXPECT_TX(mb, STAGEB);
            BULK_G2S(dst,            gAh + tA + ko, SPLB, mb);
            BULK_G2S(dst +   SPLB,   gAl + tA + ko, SPLB, mb);
            BULK_G2S(dst + 2*SPLB,   gBh + tB + ko, SPLB, mb);
            BULK_G2S(dst + 3*SPLB,   gBl + tB + ko, SPLB, mb);
        }
    }

    float acc[16][4];
    #pragma unroll
    for (int i = 0; i < 16; i++)
        #pragma unroll
        for (int j = 0; j < 4; j++) acc[i][j] = 0.f;

    // ldmatrix base offsets (per-thread, fixed modulo stage base)
    const uint32_t aoff = tile_off((uint32_t)(wr * 64 + (lane & 15)),
                                   (uint32_t)((lane >> 4) << 3));
    const uint32_t boff = 2 * SPLB +
        tile_off((uint32_t)(wc * 32 + ((lane >> 4) << 3) + (lane & 7)),
                 (uint32_t)(((lane >> 3) & 1) << 3));

    const int lq = lane & 3;
    const int lr = lane >> 2;
    const int lk = lq << 1;

    #pragma unroll 1
    for (int c = 0; c < 128; c++) {
        const int s = c % NSTG;
        const int rnd = c / NSTG;
        MBAR_WAIT(mbf + s * 8, rnd & 1);
        const uint32_t sb = smb + s * STAGEB;

        #pragma unroll
        for (int ks = 0; ks < 2; ks++) {
            const uint32_t kx = (uint32_t)(ks << 5);       // ^32 per k halfstep
            uint32_t bhf[4][2], blf[4][2];
            #pragma unroll
            for (int p = 0; p < 2; p++) {
                const uint32_t ba = sb + ((boff + p * 1024u) ^ kx);
                LDSM4(bhf[2*p][0], bhf[2*p][1], bhf[2*p+1][0], bhf[2*p+1][1], ba);
                LDSM4(blf[2*p][0], blf[2*p][1], blf[2*p+1][0], blf[2*p+1][1], ba + SPLB);
            }
            #pragma unroll
            for (int mi = 0; mi < 4; mi++) {
                const uint32_t aa = sb + ((aoff + mi * 1024u) ^ kx);
                uint32_t ahf[4], alf[4];
                LDSM4(ahf[0], ahf[1], ahf[2], ahf[3], aa);
                LDSM4(alf[0], alf[1], alf[2], alf[3], aa + SPLB);
                #pragma unroll
                for (int ni = 0; ni < 4; ni++) {
                    MMA16816(acc[mi * 4 + ni], ahf, bhf[ni]);
                    MMA16816(acc[mi * 4 + ni], ahf, blf[ni]);
                    MMA16816(acc[mi * 4 + ni], alf, bhf[ni]);
                }
            }
        }
        // non-blocking: this thread is done reading stage s for round rnd
        MBAR_ARRIVE(mbe + s * 8);
        // producer: wait until ALL threads released stage s, then refill it
        if (tid == 0 && c + NSTG < 128) {
            MBAR_WAIT(mbe + s * 8, rnd & 1);
            const uint32_t mb = mbf + s * 8;
            const uint32_t dst = smb + s * STAGEB;
            const uint64_t ko = (uint64_t)(c + NSTG) * 8192;
            MBAR_EXPECT_TX(mb, STAGEB);
            BULK_G2S(dst,            gAh + tA + ko, SPLB, mb);
            BULK_G2S(dst +   SPLB,   gAl + tA + ko, SPLB, mb);
            BULK_G2S(dst + 2*SPLB,   gBh + tB + ko, SPLB, mb);
            BULK_G2S(dst + 3*SPLB,   gBl + tB + ko, SPLB, mb);
        }
    }

    // epilogue (acc is register-private; no sync needed)
    #pragma unroll
    for (int mi = 0; mi < 4; mi++) {
        const int r = row0 + wr * 64 + mi * 16 + lr;
        #pragma unroll
        for (int ni = 0; ni < 4; ni++) {
            const int cc = col0 + wc * 32 + ni * 8 + lk;
            float b0 = 0.f, b1 = 0.f;
            if (bias) { b0 = __ldg(bias + cc); b1 = __ldg(bias + cc + 1); }
            float* p0 = C + (size_t)r * ldC + cc;
            float* p1 = C + (size_t)(r + 8) * ldC + cc;
            p0[0] = acc[mi * 4 + ni][0] + b0;
            p0[1] = acc[mi * 4 + ni][1] + b1;
            p1[0] = acc[mi * 4 + ni][2] + b0;
            p1[1] = acc[mi * 4 + ni][3] + b1;
        }
    }
}

// ---------------------------------------------------------------------------
// RoPE (in place, float4)
// ---------------------------------------------------------------------------
__global__ void rope_kernel(float* __restrict__ x, const float* __restrict__ cs,
                            const float* __restrict__ sn, int nheads, int rowstride, int total)
{
    int p = blockIdx.x * blockDim.x + threadIdx.x;
    if (p >= total) return;
    const int d    = (p & 15) << 2;
    const int h    = (p >> 4) % nheads;
    const int sidx = p / (16 * nheads);
    float* base = x + (size_t)sidx * rowstride + h * HDC;
    const float* cb = cs + (size_t)sidx * HDC;
    const float* sb = sn + (size_t)sidx * HDC;
    const float4 x1 = *(const float4*)(base + d);
    const float4 x2 = *(const float4*)(base + d + 64);
    const float4 c1 = *(const float4*)(cb + d),      s1 = *(const float4*)(sb + d);
    const float4 c2 = *(const float4*)(cb + d + 64), s2 = *(const float4*)(sb + d + 64);
    float4 o1, o2;
    o1.x = x1.x * c1.x - x2.x * s1.x;  o1.y = x1.y * c1.y - x2.y * s1.y;
    o1.z = x1.z * c1.z - x2.z * s1.z;  o1.w = x1.w * c1.w - x2.w * s1.w;
    o2.x = x2.x * c2.x + x1.x * s2.x;  o2.y = x2.y * c2.y + x1.y * s2.y;
    o2.z = x2.z * c2.z + x1.z * s2.z;  o2.w = x2.w * c2.w + x1.w * s2.w;
    *(float4*)(base + d)      = o1;
    *(float4*)(base + d + 64) = o2;
}

// ---------------------------------------------------------------------------
// Flash attention on mma.sync bf16 with hi/lo split (3-term).
// Br=128 q-rows per CTA, Bc=64 keys per tile, 8 warps (4 row-groups x 2 col).
// Output written directly as (hi,lo) bf16 in the TILED layout for the O-GEMM.
// ---------------------------------------------------------------------------
#define ALD    136
#define PLD    72
#define OFF_QL (128*ALD*2)
#define OFF_KA (2*128*ALD*2)
#define OFF_KB (OFF_KA + 18432)
#define OFF_PH (OFF_KB + 18432)
#define OFF_PL (OFF_PH + 128*PLD*2)
#define OFF_MX (OFF_PL + 128*PLD*2)
#define OFF_SM (OFF_MX + 1024)
#define ATTN_SMEM (OFF_SM + 1024)
#define SCALE 0.08838834764831845f

__device__ __forceinline__ void split_st4(float4 v, bf16* dh, bf16* dl) {
    bf16 h0 = __float2bfloat16(v.x), h1 = __float2bfloat16(v.y);
    bf16 h2 = __float2bfloat16(v.z), h3 = __float2bfloat16(v.w);
    ((__nv_bfloat162*)dh)[0] = __halves2bfloat162(h0, h1);
    ((__nv_bfloat162*)dh)[1] = __halves2bfloat162(h2, h3);
    ((__nv_bfloat162*)dl)[0] = __halves2bfloat162(
        __float2bfloat16(v.x - __bfloat162float(h0)),
        __float2bfloat16(v.y - __bfloat162float(h1)));
    ((__nv_bfloat162*)dl)[1] = __halves2bfloat162(
        __float2bfloat16(v.z - __bfloat162float(h2)),
        __float2bfloat16(v.w - __bfloat162float(h3)));
}

__global__ void __launch_bounds__(256, 1)
attn_mma(const float* __restrict__ Q, const float* __restrict__ KV,
         bf16* __restrict__ Oh, bf16* __restrict__ Ol)
{
    extern __shared__ char sm[];
    bf16*  sQh = (bf16*)(sm);
    bf16*  sQl = (bf16*)(sm + OFF_QL);
    bf16*  sKh = (bf16*)(sm + OFF_KA);    // union: K hi | Vt hi
    bf16*  sKl = (bf16*)(sm + OFF_KB);    // union: K lo | Vt lo
    bf16*  sPh = (bf16*)(sm + OFF_PH);
    bf16*  sPl = (bf16*)(sm + OFF_PL);
    float* sMax = (float*)(sm + OFF_MX);
    float* sSum = (float*)(sm + OFF_SM);

    const int tid = threadIdx.x, lane = tid & 31, wid = tid >> 5;
    const int wr = wid >> 1, wc = wid & 1;
    const int lr = lane >> 2, lq = lane & 3;
    const int qt = blockIdx.x, head = blockIdx.y, b = blockIdx.z;
    const int kvh = head >> 2;

    {
        const float* qb = Q + ((size_t)(b * SS + qt * 128) * NHC + head) * HDC;
        #pragma unroll
        for (int i = 0; i < 16; i++) {
            const int id = tid + (i << 8);
            const int row = id >> 5, d0 = (id & 31) << 2;
            float4 v = *(const float4*)(qb + (size_t)row * (NHC * HDC) + d0);
            v.x *= SCALE; v.y *= SCALE; v.z *= SCALE; v.w *= SCALE;
            split_st4(v, sQh + row * ALD + d0, sQl + row * ALD + d0);
        }
    }

    float m[2][2], l[2][2];
    #pragma unroll
    for (int i = 0; i < 2; i++)
        #pragma unroll
        for (int j = 0; j < 2; j++) { m[i][j] = -INFINITY; l[i][j] = 0.f; }
    float oacc[2][8][4];
    #pragma unroll
    for (int a = 0; a < 2; a++)
        #pragma unroll
        for (int n = 0; n < 8; n++)
            #pragma unroll
            for (int r = 0; r < 4; r++) oacc[a][n][r] = 0.f;

    #pragma unroll 1
    for (int kt = 0; kt < SS / 64; kt++) {
        __syncthreads();

        {
            const float* kb = KV + (size_t)(b * SS + kt * 64) * KVW + kvh * HDC;
            #pragma unroll
            for (int i = 0; i < 8; i++) {
                const int id = tid + (i << 8);
                const int row = id >> 5, d0 = (id & 31) << 2;
                float4 v = *(const float4*)(kb + (size_t)row * KVW + d0);
                split_st4(v, sKh + row * ALD + d0, sKl + row * ALD + d0);
            }
        }
        __syncthreads();

        float sc[2][4][4];
        #pragma unroll
        for (int a = 0; a < 2; a++)
            #pragma unroll
            for (int n = 0; n < 4; n++)
                #pragma unroll
                for (int r = 0; r < 4; r++) sc[a][n][r] = 0.f;

        #pragma unroll
        for (int ks = 0; ks < 8; ks++) {
            const int k0 = (ks << 4) + (lq << 1);
            uint32_t bh[4][2], bl[4][2];
            #pragma unroll
            for (int ni = 0; ni < 4; ni++) {
                const int n = wc * 32 + ni * 8 + lr;
                bh[ni][0] = *(const uint32_t*)(sKh + n * ALD + k0);
                bh[ni][1] = *(const uint32_t*)(sKh + n * ALD + k0 + 8);
                bl[ni][0] = *(const uint32_t*)(sKl + n * ALD + k0);
                bl[ni][1] = *(const uint32_t*)(sKl + n * ALD + k0 + 8);
            }
            #pragma unroll
            for (int mi = 0; mi < 2; mi++) {
                const int r = wr * 32 + mi * 16 + lr;
                uint32_t ah[4], al[4];
                ah[0] = *(const uint32_t*)(sQh + r * ALD + k0);
                ah[1] = *(const uint32_t*)(sQh + (r + 8) * ALD + k0);
                ah[2] = *(const uint32_t*)(sQh + r * ALD + k0 + 8);
                ah[3] = *(const uint32_t*)(sQh + (r + 8) * ALD + k0 + 8);
                al[0] = *(const uint32_t*)(sQl + r * ALD + k0);
                al[1] = *(const uint32_t*)(sQl + (r + 8) * ALD + k0);
                al[2] = *(const uint32_t*)(sQl + r * ALD + k0 + 8);
                al[3] = *(const uint32_t*)(sQl + (r + 8) * ALD + k0 + 8);
                #pragma unroll
                for (int ni = 0; ni < 4; ni++) {
                    MMA16816(sc[mi][ni], ah, bh[ni]);
                    MMA16816(sc[mi][ni], ah, bl[ni]);
                    MMA16816(sc[mi][ni], al, bh[ni]);
                }
            }
        }

        #pragma unroll
        for (int mi = 0; mi < 2; mi++)
            #pragma unroll
            for (int hf = 0; hf < 2; hf++) {
                float mx = -INFINITY;
                #pragma unroll
                for (int ni = 0; ni < 4; ni++)
                    mx = fmaxf(mx, fmaxf(sc[mi][ni][2*hf], sc[mi][ni][2*hf+1]));
                mx = fmaxf(mx, __shfl_xor_sync(0xffffffffu, mx, 1));
                mx = fmaxf(mx, __shfl_xor_sync(0xffffffffu, mx, 2));
                if (lq == 0)
                    sMax[(wr * 32 + mi * 16 + lr + 8 * hf) * 2 + wc] = mx;
            }
        __syncthreads();

        float corr[2][2];
        #pragma unroll
        for (int mi = 0; mi < 2; mi++)
            #pragma unroll
            for (int hf = 0; hf < 2; hf++) {
                const int row = wr * 32 + mi * 16 + lr + 8 * hf;
                const float tmax = fmaxf(sMax[row * 2], sMax[row * 2 + 1]);
                const float mnew = fmaxf(m[mi][hf], tmax);
                corr[mi][hf] = __expf(m[mi][hf] - mnew);
                m[mi][hf] = mnew;
                float rs = 0.f;
                #pragma unroll
                for (int ni = 0; ni < 4; ni++) {
                    const float e0 = __expf(sc[mi][ni][2*hf]   - mnew);
                    const float e1 = __expf(sc[mi][ni][2*hf+1] - mnew);
                    rs += e0 + e1;
                    const bf16 h0 = __float2bfloat16(e0);
                    const bf16 h1 = __float2bfloat16(e1);
                    const int cc = wc * 32 + ni * 8 + (lq << 1);
                    *(__nv_bfloat162*)(sPh + row * PLD + cc) = __halves2bfloat162(h0, h1);
                    *(__nv_bfloat162*)(sPl + row * PLD + cc) = __halves2bfloat162(
                        __float2bfloat16(e0 - __bfloat162float(h0)),
                        __float2bfloat16(e1 - __bfloat162float(h1)));
                }
                rs += __shfl_xor_sync(0xffffffffu, rs, 1);
                rs += __shfl_xor_sync(0xffffffffu, rs, 2);
                if (lq == 0) sSum[row * 2 + wc] = rs;
                #pragma unroll
                for (int ni = 0; ni < 8; ni++) {
                    oacc[mi][ni][2*hf]   *= corr[mi][hf];
                    oacc[mi][ni][2*hf+1] *= corr[mi][hf];
                }
            }

        {
            const int kv0  = (tid & 31) * 2;
            const int dblk = (tid >> 5) * 16;
            const float* vb = KV + (size_t)(b * SS + kt * 64 + kv0) * KVW
                             + NKVC * HDC + kvh * HDC + dblk;
            #pragma unroll
            for (int j = 0; j < 4; j++) {
                const float4 v0 = *(const float4*)(vb + j * 4);
                const float4 v1 = *(const float4*)(vb + KVW + j * 4);
                const float e0[4] = {v0.x, v0.y, v0.z, v0.w};
                const float e1[4] = {v1.x, v1.y, v1.z, v1.w};
                #pragma unroll
                for (int e = 0; e < 4; e++) {
                    const int d = dblk + j * 4 + e;
                    const bf16 a0 = __float2bfloat16(e0[e]);
                    const bf16 a1 = __float2bfloat16(e1[e]);
                    *(__nv_bfloat162*)(sKh + d * PLD + kv0) = __halves2bfloat162(a0, a1);
                    *(__nv_bfloat162*)(sKl + d * PLD + kv0) = __halves2bfloat162(
                        __float2bfloat16(e0[e] - __bfloat162float(a0)),
                        __float2bfloat16(e1[e] - __bfloat162float(a1)));
                }
            }
        }
        __syncthreads();

        #pragma unroll
        for (int mi = 0; mi < 2; mi++)
            #pragma unroll
            for (int hf = 0; hf < 2; hf++) {
                const int row = wr * 32 + mi * 16 + lr + 8 * hf;
                l[mi][hf] = l[mi][hf] * corr[mi][hf] + sSum[row * 2] + sSum[row * 2 + 1];
            }

        #pragma unroll
        for (int ks = 0; ks < 4; ks++) {
            const int k0 = (ks << 4) + (lq << 1);
            #pragma unroll
            for (int mi = 0; mi < 2; mi++) {
                const int r = wr * 32 + mi * 16 + lr;
                uint32_t ph[4], pl[4];
                ph[0] = *(const uint32_t*)(sPh + r * PLD + k0);
                ph[1] = *(const uint32_t*)(sPh + (r + 8) * PLD + k0);
                ph[2] = *(const uint32_t*)(sPh + r * PLD + k0 + 8);
                ph[3] = *(const uint32_t*)(sPh + (r + 8) * PLD + k0 + 8);
                pl[0] = *(const uint32_t*)(sPl + r * PLD + k0);
                pl[1] = *(const uint32_t*)(sPl + (r + 8) * PLD + k0);
                pl[2] = *(const uint32_t*)(sPl + r * PLD + k0 + 8);
                pl[3] = *(const uint32_t*)(sPl + (r + 8) * PLD + k0 + 8);
                #pragma unroll
                for (int ni = 0; ni < 8; ni++) {
                    const int n = wc * 64 + ni * 8 + lr;
                    uint32_t vh[2], vl[2];
                    vh[0] = *(const uint32_t*)(sKh + n * PLD + k0);
                    vh[1] = *(const uint32_t*)(sKh + n * PLD + k0 + 8);
                    vl[0] = *(const uint32_t*)(sKl + n * PLD + k0);
                    vl[1] = *(const uint32_t*)(sKl + n * PLD + k0 + 8);
                    MMA16816(oacc[mi][ni], ph, vh);
                    MMA16816(oacc[mi][ni], ph, vl);
                    MMA16816(oacc[mi][ni], pl, vh);
                }
            }
        }
    }

    // ---- epilogue: normalize, split, store bf16 hi/lo in TILED layout ----
    #pragma unroll
    for (int mi = 0; mi < 2; mi++)
        #pragma unroll
        for (int hf = 0; hf < 2; hf++) {
            const int row = wr * 32 + mi * 16 + lr + 8 * hf;
            const size_t rowg = (size_t)(b * SS + qt * 128 + row);
            const float inv = 1.f / l[mi][hf];
            #pragma unroll
            for (int ni = 0; ni < 8; ni++) {
                const int colg = head * 128 + wc * 64 + ni * 8 + (lq << 1);
                const float o0 = oacc[mi][ni][2*hf]   * inv;
                const float o1 = oacc[mi][ni][2*hf+1] * inv;
                const bf16 h0 = __float2bfloat16(o0);
                const bf16 h1 = __float2bfloat16(o1);
                const size_t   tb  = ((rowg >> 7) * 128 + (size_t)(colg >> 5)) * 8192;
                const uint32_t off = tile_off((uint32_t)(rowg & 127), colg & 31);
                *(__nv_bfloat162*)((char*)Oh + tb + off) = __halves2bfloat162(h0, h1);
                *(__nv_bfloat162*)((char*)Ol + tb + off) = __halves2bfloat162(
                    __float2bfloat16(o0 - __bfloat162float(h0)),
                    __float2bfloat16(o1 - __bfloat162float(h1)));
            }
        }
}

// ---------------------------------------------------------------------------
// Launch
// ---------------------------------------------------------------------------
extern "C" void kernel_launch(void* const* d_in, const int* in_sizes, int n_in,
                              void* d_out, int out_size)
{
    (void)in_sizes; (void)n_in; (void)out_size;
    const float* hidden = (const float*)d_in[0];
    const float* cosp   = (const float*)d_in[1];
    const float* sinp   = (const float*)d_in[2];
    const float* Wq     = (const float*)d_in[3];
    const float* bq     = (const float*)d_in[4];
    const float* Wk     = (const float*)d_in[5];
    const float* bk     = (const float*)d_in[6];
    const float* Wv     = (const float*)d_in[7];
    const float* bv     = (const float*)d_in[8];
    const float* Wo     = (const float*)d_in[9];
    float* out = (float*)d_out;

    bf16 *ah, *al, *wqh, *wql, *wkvh, *wkvl, *woh, *wol, *oth, *otl;
    float *q, *kv, *bkv;
    cudaGetSymbolAddress((void**)&ah,   g_ah);
    cudaGetSymbolAddress((void**)&al,   g_al);
    cudaGetSymbolAddress((void**)&wqh,  g_wqh);
    cudaGetSymbolAddress((void**)&wql,  g_wql);
    cudaGetSymbolAddress((void**)&wkvh, g_wkvh);
    cudaGetSymbolAddress((void**)&wkvl, g_wkvl);
    cudaGetSymbolAddress((void**)&woh,  g_woh);
    cudaGetSymbolAddress((void**)&wol,  g_wol);
    cudaGetSymbolAddress((void**)&oth,  g_oth);
    cudaGetSymbolAddress((void**)&otl,  g_otl);
    cudaGetSymbolAddress((void**)&q,    g_q);
    cudaGetSymbolAddress((void**)&kv,   g_kv);
    cudaGetSymbolAddress((void**)&bkv,  g_bkv);

    cudaFuncSetAttribute(gemm_mma,
                         cudaFuncAttributeMaxDynamicSharedMemorySize, GSMEM);
    cudaFuncSetAttribute(attn_mma,
                         cudaFuncAttributeMaxDynamicSharedMemorySize, ATTN_SMEM);

    const dim3 tb(32, 8);
    // pre-passes: activation split + weight split-transpose (tiled layout)
    {
        const int t8 = MROWS * HIDC / 8;
        split_kernel<<<(t8 + 255) / 256, 256>>>(hidden, ah, al, t8);
    }
    wsplitT_kernel<<<dim3(HIDC / 32, GK / 32), tb>>>(Wq, wqh, wql, HIDC);
    // K into n[0,1024), V into n[1024,2048) of the combined tiled buffer
    wsplitT_kernel<<<dim3((NKVC * HDC) / 32, GK / 32), tb>>>(Wk, wkvh, wkvl, NKVC * HDC);
    wsplitT_kernel<<<dim3((NKVC * HDC) / 32, GK / 32), tb>>>(
        Wv, wkvh + (size_t)(NKVC * HDC) * GK, wkvl + (size_t)(NKVC * HDC) * GK, NKVC * HDC);
    wsplitT_kernel<<<dim3(HIDC / 32, GK / 32), tb>>>(Wo, woh, wol, HIDC);
    concat_bias<<<(KVW + 255) / 256, 256>>>(bk, bv, bkv);

    // projections (tensor path, bulk-fed, ldmatrix loads, sync-free pipeline)
    gemm_mma<<<dim3(HIDC / 128, MROWS / 128), 256, GSMEM>>>(ah, al, wqh, wql, bq, q, HIDC);
    gemm_mma<<<dim3(KVW  / 128, MROWS / 128), 256, GSMEM>>>(ah, al, wkvh, wkvl, bkv, kv, KVW);

    // RoPE on q and k-part of kv
    const int tq = MROWS * NHC * 16;
    rope_kernel<<<(tq + 255) / 256, 256>>>(q, cosp, sinp, NHC, NHC * HDC, tq);
    const int tk = MROWS * NKVC * 16;
    rope_kernel<<<(tk + 255) / 256, 256>>>(kv, cosp, sinp, NKVC, KVW, tk);

    // attention (tensor path, writes tiled split bf16 output)
    attn_mma<<<dim3(SS / 128, NHC, BB), 256, ATTN_SMEM>>>(q, kv, oth, otl);

    // output projection
    gemm_mma<<<dim3(HIDC / 128, MROWS / 128), 256, GSMEM>>>(oth, otl, woh, wol, nullptr, out, HIDC);
}